// round 1
// baseline (speedup 1.0000x reference)
#include <cuda_runtime.h>
#include <cuda_bf16.h>
#include <math.h>

#define N_NODES 50000
#define N_EDGES 1600000
#define IN_DIM 512
#define HID_DIM 256
#define OUT_DIM 64
#define K_HOPS 4
#define ALPHA 0.1f

// ---------------- device scratch (no allocs allowed) ----------------
__device__ float g_hidden[(size_t)N_NODES * HID_DIM];   // 51.2 MB
__device__ float g_x0[(size_t)N_NODES * OUT_DIM];       // feat0 (post-MLP)
__device__ float g_fA[(size_t)N_NODES * OUT_DIM];
__device__ float g_fB[(size_t)N_NODES * OUT_DIM];
__device__ int   g_deg_out[N_NODES];
__device__ int   g_deg_in[N_NODES];
__device__ int   g_fill[N_NODES];
__device__ int   g_row_ptr[N_NODES + 1];
__device__ float g_nsrc[N_NODES];
__device__ float g_ndst[N_NODES];
__device__ int   g_csr_src[N_EDGES];
__device__ int   g_csr_eid[N_EDGES];
__device__ float g_es[N_NODES];
__device__ float g_ed[N_NODES];

// ---------------- small kernels ----------------
__global__ void zero3_kernel() {
    int i = blockIdx.x * blockDim.x + threadIdx.x;
    if (i < N_NODES) {
        g_deg_out[i] = 0;
        g_deg_in[i]  = 0;
        g_fill[i]    = 0;
    }
}

__global__ void count_deg_kernel(const int* __restrict__ src, const int* __restrict__ dst) {
    int e = blockIdx.x * blockDim.x + threadIdx.x;
    if (e < N_EDGES) {
        atomicAdd(&g_deg_out[src[e]], 1);
        atomicAdd(&g_deg_in[dst[e]], 1);
    }
}

__global__ void norm_kernel() {
    int i = blockIdx.x * blockDim.x + threadIdx.x;
    if (i < N_NODES) {
        int doo = g_deg_out[i]; if (doo < 1) doo = 1;
        int din = g_deg_in[i];  if (din < 1) din = 1;
        g_nsrc[i] = rsqrtf((float)doo);
        g_ndst[i] = rsqrtf((float)din);
    }
}

// exclusive scan of g_deg_in -> g_row_ptr, single block of 1024 threads
__global__ void scan_kernel() {
    __shared__ int warpsum[32];
    __shared__ int carry_s;
    const int n = N_NODES;
    int tid = threadIdx.x, lane = tid & 31, wid = tid >> 5;
    if (tid == 0) carry_s = 0;
    __syncthreads();
    for (int base = 0; base < n; base += 1024) {
        int i = base + tid;
        int v = (i < n) ? g_deg_in[i] : 0;
        int x = v;
        #pragma unroll
        for (int off = 1; off < 32; off <<= 1) {
            int t = __shfl_up_sync(0xffffffffu, x, off);
            if (lane >= off) x += t;
        }
        if (lane == 31) warpsum[wid] = x;
        __syncthreads();
        if (wid == 0) {
            int w = warpsum[lane];
            #pragma unroll
            for (int off = 1; off < 32; off <<= 1) {
                int t = __shfl_up_sync(0xffffffffu, w, off);
                if (lane >= off) w += t;
            }
            warpsum[lane] = w;
        }
        __syncthreads();
        int carry = carry_s;
        int offset = (wid > 0) ? warpsum[wid - 1] : 0;
        int incl = x + offset;
        if (i < n) g_row_ptr[i] = carry + incl - v;
        __syncthreads();
        if (tid == 1023) carry_s = carry + warpsum[31];
        __syncthreads();
    }
    if (tid == 0) g_row_ptr[n] = carry_s;
}

__global__ void build_csr_kernel(const int* __restrict__ src, const int* __restrict__ dst) {
    int e = blockIdx.x * blockDim.x + threadIdx.x;
    if (e < N_EDGES) {
        int d = dst[e];
        int pos = g_row_ptr[d] + atomicAdd(&g_fill[d], 1);
        g_csr_src[pos] = src[e];
        g_csr_eid[pos] = e;
    }
}

// ---------------- tiled SGEMM: C = act(A @ B + bias) ----------------
template <int BM, int BN, int BK, int TM, int TN, bool RELU>
__global__ __launch_bounds__((BM / TM) * (BN / TN))
void gemm_bias_kernel(const float* __restrict__ A, const float* __restrict__ B,
                      const float* __restrict__ bias, float* __restrict__ C,
                      int M, int N, int K) {
    constexpr int TX = BN / TN;
    constexpr int TY = BM / TM;
    constexpr int NT = TX * TY;
    __shared__ float As[BK][BM];
    __shared__ float Bs[BK][BN];
    int tid = threadIdx.x;
    int tcol = tid % TX, trow = tid / TX;
    int rowBase = blockIdx.y * BM;
    int colBase = blockIdx.x * BN;
    float acc[TM][TN];
    #pragma unroll
    for (int i = 0; i < TM; i++)
        #pragma unroll
        for (int j = 0; j < TN; j++) acc[i][j] = 0.f;

    for (int k0 = 0; k0 < K; k0 += BK) {
        // load A tile (BM x BK), float4 along K, transpose into As[k][m]
        #pragma unroll
        for (int i = tid; i < BM * BK / 4; i += NT) {
            int r = i / (BK / 4);
            int c4 = (i % (BK / 4)) * 4;
            int row = rowBase + r;
            float4 v = make_float4(0.f, 0.f, 0.f, 0.f);
            if (row < M) v = *(const float4*)&A[(size_t)row * K + k0 + c4];
            As[c4 + 0][r] = v.x; As[c4 + 1][r] = v.y;
            As[c4 + 2][r] = v.z; As[c4 + 3][r] = v.w;
        }
        // load B tile (BK x BN)
        #pragma unroll
        for (int i = tid; i < BK * BN / 4; i += NT) {
            int r = i / (BN / 4);
            int c4 = (i % (BN / 4)) * 4;
            *(float4*)&Bs[r][c4] = *(const float4*)&B[(size_t)(k0 + r) * N + colBase + c4];
        }
        __syncthreads();
        #pragma unroll
        for (int kk = 0; kk < BK; kk++) {
            float a[TM], b[TN];
            #pragma unroll
            for (int i = 0; i < TM; i++) a[i] = As[kk][trow * TM + i];
            #pragma unroll
            for (int j = 0; j < TN; j++) b[j] = Bs[kk][tcol * TN + j];
            #pragma unroll
            for (int i = 0; i < TM; i++)
                #pragma unroll
                for (int j = 0; j < TN; j++) acc[i][j] += a[i] * b[j];
        }
        __syncthreads();
    }
    #pragma unroll
    for (int i = 0; i < TM; i++) {
        int row = rowBase + trow * TM + i;
        if (row >= M) continue;
        #pragma unroll
        for (int j = 0; j < TN; j++) {
            int col = colBase + tcol * TN + j;
            float v = acc[i][j] + bias[col];
            if (RELU) v = fmaxf(v, 0.f);
            C[(size_t)row * N + col] = v;
        }
    }
}

// ---------------- propagation hop: warp per node, CSR gather ----------------
__global__ void prop_kernel(const float* __restrict__ fin, float* __restrict__ fout) {
    int node = (blockIdx.x * blockDim.x + threadIdx.x) >> 5;
    if (node >= N_NODES) return;
    int lane = threadIdx.x & 31;
    int beg = g_row_ptr[node], end = g_row_ptr[node + 1];
    float ax = 0.f, ay = 0.f;
    for (int p = beg; p < end; p++) {
        int s = g_csr_src[p];
        float ns = g_nsrc[s];
        float2 v = ((const float2*)(fin + (size_t)s * OUT_DIM))[lane];
        ax += v.x * ns;
        ay += v.y * ns;
    }
    float nd = g_ndst[node];
    float2 z = ((const float2*)(g_x0 + (size_t)node * OUT_DIM))[lane];
    float2 o;
    o.x = (1.f - ALPHA) * ax * nd + ALPHA * z.x;
    o.y = (1.f - ALPHA) * ay * nd + ALPHA * z.y;
    ((float2*)(fout + (size_t)node * OUT_DIM))[lane] = o;
}

// ---------------- attention score dots: warp per node ----------------
__global__ void dots_kernel(const float* __restrict__ feat,
                            const float* __restrict__ wsrc,
                            const float* __restrict__ wdst) {
    int node = (blockIdx.x * blockDim.x + threadIdx.x) >> 5;
    if (node >= N_NODES) return;
    int lane = threadIdx.x & 31;
    float2 f = ((const float2*)(feat + (size_t)node * OUT_DIM))[lane];
    float2 a = ((const float2*)wsrc)[lane];
    float2 b = ((const float2*)wdst)[lane];
    float s = f.x * a.x + f.y * a.y;
    float d = f.x * b.x + f.y * b.y;
    #pragma unroll
    for (int off = 16; off; off >>= 1) {
        s += __shfl_xor_sync(0xffffffffu, s, off);
        d += __shfl_xor_sync(0xffffffffu, d, off);
    }
    if (lane == 0) {
        g_es[node] = s;
        g_ed[node] = d;
    }
}

// ---------------- attention softmax over in-edges: warp per node ----------------
__global__ void attn_kernel(float* __restrict__ attn_out) {
    int node = (blockIdx.x * blockDim.x + threadIdx.x) >> 5;
    if (node >= N_NODES) return;
    int lane = threadIdx.x & 31;
    int beg = g_row_ptr[node], end = g_row_ptr[node + 1];
    if (beg == end) return;
    float edv = g_ed[node];
    float m = -INFINITY;
    for (int p = beg + lane; p < end; p += 32) {
        float e = tanhf(g_es[g_csr_src[p]] + edv);
        m = fmaxf(m, e);
    }
    #pragma unroll
    for (int off = 16; off; off >>= 1) m = fmaxf(m, __shfl_xor_sync(0xffffffffu, m, off));
    float s = 0.f;
    for (int p = beg + lane; p < end; p += 32) {
        float e = tanhf(g_es[g_csr_src[p]] + edv);
        s += expf(e - m);
    }
    #pragma unroll
    for (int off = 16; off; off >>= 1) s += __shfl_xor_sync(0xffffffffu, s, off);
    float inv = 1.f / s;
    for (int p = beg + lane; p < end; p += 32) {
        float e = tanhf(g_es[g_csr_src[p]] + edv);
        attn_out[g_csr_eid[p]] = expf(e - m) * inv;
    }
}

// ---------------- log_softmax over 64 features: warp per node ----------------
__global__ void lsm_kernel(const float* __restrict__ feat, float* __restrict__ out) {
    int node = (blockIdx.x * blockDim.x + threadIdx.x) >> 5;
    if (node >= N_NODES) return;
    int lane = threadIdx.x & 31;
    float2 f = ((const float2*)(feat + (size_t)node * OUT_DIM))[lane];
    float m = fmaxf(f.x, f.y);
    #pragma unroll
    for (int off = 16; off; off >>= 1) m = fmaxf(m, __shfl_xor_sync(0xffffffffu, m, off));
    float s = expf(f.x - m) + expf(f.y - m);
    #pragma unroll
    for (int off = 16; off; off >>= 1) s += __shfl_xor_sync(0xffffffffu, s, off);
    float lse = m + logf(s);
    float2 o;
    o.x = f.x - lse;
    o.y = f.y - lse;
    ((float2*)(out + (size_t)node * OUT_DIM))[lane] = o;
}

// ---------------- launch ----------------
extern "C" void kernel_launch(void* const* d_in, const int* in_sizes, int n_in,
                              void* d_out, int out_size) {
    const float* h   = (const float*)d_in[0];
    const int*   src = (const int*)d_in[1];
    const int*   dst = (const int*)d_in[2];
    const float* W1  = (const float*)d_in[3];
    const float* b1  = (const float*)d_in[4];
    const float* W2  = (const float*)d_in[5];
    const float* b2  = (const float*)d_in[6];
    const float* wsr = (const float*)d_in[7];
    const float* wds = (const float*)d_in[8];
    float* out = (float*)d_out;

    float *p_hidden, *p_x0, *p_fA, *p_fB;
    cudaGetSymbolAddress((void**)&p_hidden, g_hidden);
    cudaGetSymbolAddress((void**)&p_x0, g_x0);
    cudaGetSymbolAddress((void**)&p_fA, g_fA);
    cudaGetSymbolAddress((void**)&p_fB, g_fB);

    const int TPB = 256;
    int nodeBlocks = (N_NODES + TPB - 1) / TPB;                // per-thread node kernels
    int edgeBlocks = (N_EDGES + TPB - 1) / TPB;                // per-thread edge kernels
    int warpNodeBlocks = (N_NODES * 32 + TPB - 1) / TPB;       // warp-per-node kernels

    // graph structure
    zero3_kernel<<<nodeBlocks, TPB>>>();
    count_deg_kernel<<<edgeBlocks, TPB>>>(src, dst);
    norm_kernel<<<nodeBlocks, TPB>>>();
    scan_kernel<<<1, 1024>>>();
    build_csr_kernel<<<edgeBlocks, TPB>>>(src, dst);

    // MLP: hidden = relu(h @ W1 + b1);  x0 = hidden @ W2 + b2
    {
        dim3 grid1(HID_DIM / 128, (N_NODES + 127) / 128);
        gemm_bias_kernel<128, 128, 16, 8, 8, true><<<grid1, 256>>>(
            h, W1, b1, p_hidden, N_NODES, HID_DIM, IN_DIM);
        dim3 grid2(OUT_DIM / 64, (N_NODES + 127) / 128);
        gemm_bias_kernel<128, 64, 16, 8, 4, false><<<grid2, 256>>>(
            p_hidden, W2, b2, p_x0, N_NODES, OUT_DIM, HID_DIM);
    }

    // K_HOPS=4 propagation, ping-pong buffers; final result in g_fB
    prop_kernel<<<warpNodeBlocks, TPB>>>(p_x0, p_fA);
    prop_kernel<<<warpNodeBlocks, TPB>>>(p_fA, p_fB);
    prop_kernel<<<warpNodeBlocks, TPB>>>(p_fB, p_fA);
    prop_kernel<<<warpNodeBlocks, TPB>>>(p_fA, p_fB);

    // attention
    dots_kernel<<<warpNodeBlocks, TPB>>>(p_fB, wsr, wds);
    attn_kernel<<<warpNodeBlocks, TPB>>>(out + (size_t)N_NODES * OUT_DIM);

    // log_softmax output
    lsm_kernel<<<warpNodeBlocks, TPB>>>(p_fB, out);
}

// round 2
// speedup vs baseline: 1.7079x; 1.7079x over previous
#include <cuda_runtime.h>
#include <cuda_bf16.h>
#include <math.h>
#include <stdint.h>

#define N_NODES 50000
#define N_EDGES 1600000
#define IN_DIM 512
#define HID_DIM 256
#define OUT_DIM 64
#define K_HOPS 4
#define ALPHA 0.1f

#define SCAN_BLK 1024
#define SCAN_NBLK ((N_NODES + SCAN_BLK - 1) / SCAN_BLK)   // 49

// ---------------- device scratch (no allocs allowed) ----------------
__device__ float g_hidden[(size_t)N_NODES * HID_DIM];   // 51.2 MB
__device__ float g_x0[(size_t)N_NODES * OUT_DIM];       // feat0 (post-MLP)
__device__ float g_fA[(size_t)N_NODES * OUT_DIM];
__device__ float g_fB[(size_t)N_NODES * OUT_DIM];
__device__ int   g_deg_out[N_NODES];
__device__ int   g_deg_in[N_NODES];
__device__ int   g_fill[N_NODES];
__device__ int   g_row_ptr[N_NODES + 1];
__device__ float g_nsrc[N_NODES];
__device__ float g_ndst[N_NODES];
__device__ int   g_csr_src[N_EDGES];
__device__ int   g_csr_eid[N_EDGES];
__device__ float g_es[N_NODES];
__device__ float g_ed[N_NODES];
__device__ float g_etmp[N_EDGES];
__device__ int   g_bsum[SCAN_NBLK];
__device__ int   g_boff[SCAN_NBLK];

// ---------------- small kernels ----------------
__global__ void zero3_kernel() {
    int i = blockIdx.x * blockDim.x + threadIdx.x;
    if (i < N_NODES) {
        g_deg_out[i] = 0;
        g_deg_in[i]  = 0;
        g_fill[i]    = 0;
    }
}

__global__ void count_deg_kernel(const int* __restrict__ src, const int* __restrict__ dst) {
    int e = blockIdx.x * blockDim.x + threadIdx.x;
    if (e < N_EDGES) {
        atomicAdd(&g_deg_out[src[e]], 1);
        atomicAdd(&g_deg_in[dst[e]], 1);
    }
}

__global__ void norm_kernel() {
    int i = blockIdx.x * blockDim.x + threadIdx.x;
    if (i < N_NODES) {
        int doo = g_deg_out[i]; if (doo < 1) doo = 1;
        int din = g_deg_in[i];  if (din < 1) din = 1;
        g_nsrc[i] = rsqrtf((float)doo);
        g_ndst[i] = rsqrtf((float)din);
    }
}

// ---- 3-phase grid-wide exclusive scan of g_deg_in -> g_row_ptr ----
__global__ void scan1_kernel() {
    __shared__ int warpsum[32];
    int tid = threadIdx.x, lane = tid & 31, wid = tid >> 5;
    int i = blockIdx.x * SCAN_BLK + tid;
    int v = (i < N_NODES) ? g_deg_in[i] : 0;
    int x = v;
    #pragma unroll
    for (int off = 1; off < 32; off <<= 1) {
        int t = __shfl_up_sync(0xffffffffu, x, off);
        if (lane >= off) x += t;
    }
    if (lane == 31) warpsum[wid] = x;
    __syncthreads();
    if (wid == 0) {
        int w = warpsum[lane];
        #pragma unroll
        for (int off = 1; off < 32; off <<= 1) {
            int t = __shfl_up_sync(0xffffffffu, w, off);
            if (lane >= off) w += t;
        }
        warpsum[lane] = w;
    }
    __syncthreads();
    int offset = (wid > 0) ? warpsum[wid - 1] : 0;
    if (i < N_NODES) g_row_ptr[i] = x + offset - v;   // exclusive within block
    if (tid == SCAN_BLK - 1) g_bsum[blockIdx.x] = x + offset;
}

__global__ void scan2_kernel() {
    int run = 0;
    for (int i = 0; i < SCAN_NBLK; i++) {
        g_boff[i] = run;
        run += g_bsum[i];
    }
    g_row_ptr[N_NODES] = run;
}

__global__ void scan3_kernel() {
    int i = blockIdx.x * SCAN_BLK + threadIdx.x;
    if (i < N_NODES && blockIdx.x > 0) g_row_ptr[i] += g_boff[blockIdx.x];
}

__global__ void build_csr_kernel(const int* __restrict__ src, const int* __restrict__ dst) {
    int e = blockIdx.x * blockDim.x + threadIdx.x;
    if (e < N_EDGES) {
        int d = dst[e];
        int pos = g_row_ptr[d] + atomicAdd(&g_fill[d], 1);
        g_csr_src[pos] = src[e];
        g_csr_eid[pos] = e;
    }
}

// ---------------- tensor-core GEMM: C = act(A@B + bias) via bf16 3-split ----
// C = Ahi*Bhi + Ahi*Blo + Alo*Bhi  (error ~3e-5 rel, vs 1e-3 threshold)
__device__ __forceinline__ uint32_t smem_u32(const void* p) {
    return (uint32_t)__cvta_generic_to_shared(p);
}
__device__ __forceinline__ void ldsm_x4(uint32_t* r, uint32_t addr) {
    asm volatile("ldmatrix.sync.aligned.m8n8.x4.shared.b16 {%0,%1,%2,%3}, [%4];\n"
        : "=r"(r[0]), "=r"(r[1]), "=r"(r[2]), "=r"(r[3]) : "r"(addr));
}
__device__ __forceinline__ void ldsm_x4_trans(uint32_t* r, uint32_t addr) {
    asm volatile("ldmatrix.sync.aligned.m8n8.x4.trans.shared.b16 {%0,%1,%2,%3}, [%4];\n"
        : "=r"(r[0]), "=r"(r[1]), "=r"(r[2]), "=r"(r[3]) : "r"(addr));
}
__device__ __forceinline__ void mma16816(float* c, const uint32_t* a, const uint32_t* b) {
    asm volatile(
        "mma.sync.aligned.m16n8k16.row.col.f32.bf16.bf16.f32 "
        "{%0,%1,%2,%3}, {%4,%5,%6,%7}, {%8,%9}, {%0,%1,%2,%3};\n"
        : "+f"(c[0]), "+f"(c[1]), "+f"(c[2]), "+f"(c[3])
        : "r"(a[0]), "r"(a[1]), "r"(a[2]), "r"(a[3]), "r"(b[0]), "r"(b[1]));
}
__device__ __forceinline__ void split2(float x, float y, uint32_t& hi, uint32_t& lo) {
    __nv_bfloat16 hx = __float2bfloat16(x);
    __nv_bfloat16 hy = __float2bfloat16(y);
    __nv_bfloat16 lx = __float2bfloat16(x - __bfloat162float(hx));
    __nv_bfloat16 ly = __float2bfloat16(y - __bfloat162float(hy));
    __nv_bfloat162 h2; h2.x = hx; h2.y = hy;
    __nv_bfloat162 l2; l2.x = lx; l2.y = ly;
    hi = *(uint32_t*)&h2;
    lo = *(uint32_t*)&l2;
}

template <int BM, int BN, int BK, bool RELU>
__global__ __launch_bounds__(256)
void gemm_bf16x3_kernel(const float* __restrict__ A, const float* __restrict__ B,
                        const float* __restrict__ bias, float* __restrict__ C,
                        int M, int N, int K) {
    constexpr int WN  = BN / 2;        // warp n-extent (2 warps in n)
    constexpr int NJ  = WN / 8;        // 8-wide n tiles per warp
    constexpr int NJP = NJ / 2;        // pairs for x4.trans loads
    __shared__ __align__(16) __nv_bfloat16 As_hi[BM][BK + 8];
    __shared__ __align__(16) __nv_bfloat16 As_lo[BM][BK + 8];
    __shared__ __align__(16) __nv_bfloat16 Bs_hi[BK][BN + 8];
    __shared__ __align__(16) __nv_bfloat16 Bs_lo[BK][BN + 8];

    int tid = threadIdx.x;
    int lane = tid & 31, wid = tid >> 5;
    int wm = wid & 3, wn = wid >> 2;           // 4x2 warp grid
    int rowBase = blockIdx.y * BM;
    int colBase = blockIdx.x * BN;

    float acc[2][NJ][4];
    #pragma unroll
    for (int i = 0; i < 2; i++)
        #pragma unroll
        for (int j = 0; j < NJ; j++)
            #pragma unroll
            for (int q = 0; q < 4; q++) acc[i][j][q] = 0.f;

    for (int k0 = 0; k0 < K; k0 += BK) {
        // A tile: BM x BK floats -> split to As_hi/As_lo
        #pragma unroll
        for (int i = tid; i < BM * BK / 4; i += 256) {
            int r = i >> 3;                 // BK/4 == 8
            int c4 = (i & 7) << 2;
            int grow = rowBase + r;
            float4 v = make_float4(0.f, 0.f, 0.f, 0.f);
            if (grow < M) v = *(const float4*)&A[(size_t)grow * K + k0 + c4];
            uint32_t h0, l0, h1, l1;
            split2(v.x, v.y, h0, l0);
            split2(v.z, v.w, h1, l1);
            *(uint32_t*)&As_hi[r][c4]     = h0;
            *(uint32_t*)&As_hi[r][c4 + 2] = h1;
            *(uint32_t*)&As_lo[r][c4]     = l0;
            *(uint32_t*)&As_lo[r][c4 + 2] = l1;
        }
        // B tile: BK x BN floats
        #pragma unroll
        for (int i = tid; i < BK * BN / 4; i += 256) {
            int r = i / (BN / 4);
            int c4 = (i % (BN / 4)) << 2;
            float4 v = *(const float4*)&B[(size_t)(k0 + r) * N + colBase + c4];
            uint32_t h0, l0, h1, l1;
            split2(v.x, v.y, h0, l0);
            split2(v.z, v.w, h1, l1);
            *(uint32_t*)&Bs_hi[r][c4]     = h0;
            *(uint32_t*)&Bs_hi[r][c4 + 2] = h1;
            *(uint32_t*)&Bs_lo[r][c4]     = l0;
            *(uint32_t*)&Bs_lo[r][c4 + 2] = l1;
        }
        __syncthreads();

        #pragma unroll
        for (int kk = 0; kk < BK; kk += 16) {
            uint32_t a_hi[2][4], a_lo[2][4];
            #pragma unroll
            for (int mi = 0; mi < 2; mi++) {
                int r = wm * 32 + mi * 16 + (lane & 15);
                int c = kk + ((lane >> 4) << 3);
                ldsm_x4(a_hi[mi], smem_u32(&As_hi[r][c]));
                ldsm_x4(a_lo[mi], smem_u32(&As_lo[r][c]));
            }
            uint32_t b_hi[NJ][2], b_lo[NJ][2];
            #pragma unroll
            for (int p = 0; p < NJP; p++) {
                int r = kk + (lane & 7) + (lane & 8);
                int c = wn * WN + p * 16 + ((lane >> 4) << 3);
                uint32_t t[4];
                ldsm_x4_trans(t, smem_u32(&Bs_hi[r][c]));
                b_hi[2 * p][0] = t[0]; b_hi[2 * p][1] = t[1];
                b_hi[2 * p + 1][0] = t[2]; b_hi[2 * p + 1][1] = t[3];
                ldsm_x4_trans(t, smem_u32(&Bs_lo[r][c]));
                b_lo[2 * p][0] = t[0]; b_lo[2 * p][1] = t[1];
                b_lo[2 * p + 1][0] = t[2]; b_lo[2 * p + 1][1] = t[3];
            }
            #pragma unroll
            for (int mi = 0; mi < 2; mi++)
                #pragma unroll
                for (int nj = 0; nj < NJ; nj++) {
                    mma16816(acc[mi][nj], a_hi[mi], b_hi[nj]);
                    mma16816(acc[mi][nj], a_hi[mi], b_lo[nj]);
                    mma16816(acc[mi][nj], a_lo[mi], b_hi[nj]);
                }
        }
        __syncthreads();
    }

    // epilogue
    int g = lane >> 2, tig = lane & 3;
    #pragma unroll
    for (int mi = 0; mi < 2; mi++) {
        int row0 = rowBase + wm * 32 + mi * 16 + g;
        int row1 = row0 + 8;
        #pragma unroll
        for (int nj = 0; nj < NJ; nj++) {
            int col = colBase + wn * WN + nj * 8 + 2 * tig;
            float bv0 = bias[col], bv1 = bias[col + 1];
            if (row0 < M) {
                float v0 = acc[mi][nj][0] + bv0;
                float v1 = acc[mi][nj][1] + bv1;
                if (RELU) { v0 = fmaxf(v0, 0.f); v1 = fmaxf(v1, 0.f); }
                C[(size_t)row0 * N + col]     = v0;
                C[(size_t)row0 * N + col + 1] = v1;
            }
            if (row1 < M) {
                float v2 = acc[mi][nj][2] + bv0;
                float v3 = acc[mi][nj][3] + bv1;
                if (RELU) { v2 = fmaxf(v2, 0.f); v3 = fmaxf(v3, 0.f); }
                C[(size_t)row1 * N + col]     = v2;
                C[(size_t)row1 * N + col + 1] = v3;
            }
        }
    }
}

// ---------------- propagation hop: warp per node, CSR gather ----------------
__global__ void prop_kernel(const float* __restrict__ fin, float* __restrict__ fout) {
    int node = (blockIdx.x * blockDim.x + threadIdx.x) >> 5;
    if (node >= N_NODES) return;
    int lane = threadIdx.x & 31;
    int beg = g_row_ptr[node], end = g_row_ptr[node + 1];
    float ax = 0.f, ay = 0.f;
    for (int p = beg; p < end; p++) {
        int s = g_csr_src[p];
        float ns = g_nsrc[s];
        float2 v = ((const float2*)(fin + (size_t)s * OUT_DIM))[lane];
        ax += v.x * ns;
        ay += v.y * ns;
    }
    float nd = g_ndst[node];
    float2 z = ((const float2*)(g_x0 + (size_t)node * OUT_DIM))[lane];
    float2 o;
    o.x = (1.f - ALPHA) * ax * nd + ALPHA * z.x;
    o.y = (1.f - ALPHA) * ay * nd + ALPHA * z.y;
    ((float2*)(fout + (size_t)node * OUT_DIM))[lane] = o;
}

// ---------------- attention score dots: warp per node ----------------
__global__ void dots_kernel(const float* __restrict__ feat,
                            const float* __restrict__ wsrc,
                            const float* __restrict__ wdst) {
    int node = (blockIdx.x * blockDim.x + threadIdx.x) >> 5;
    if (node >= N_NODES) return;
    int lane = threadIdx.x & 31;
    float2 f = ((const float2*)(feat + (size_t)node * OUT_DIM))[lane];
    float2 a = ((const float2*)wsrc)[lane];
    float2 b = ((const float2*)wdst)[lane];
    float s = f.x * a.x + f.y * a.y;
    float d = f.x * b.x + f.y * b.y;
    #pragma unroll
    for (int off = 16; off; off >>= 1) {
        s += __shfl_xor_sync(0xffffffffu, s, off);
        d += __shfl_xor_sync(0xffffffffu, d, off);
    }
    if (lane == 0) {
        g_es[node] = s;
        g_ed[node] = d;
    }
}

// ---------------- attention softmax over in-edges: warp per node ----------------
__global__ void attn_kernel(float* __restrict__ attn_out) {
    int node = (blockIdx.x * blockDim.x + threadIdx.x) >> 5;
    if (node >= N_NODES) return;
    int lane = threadIdx.x & 31;
    int beg = g_row_ptr[node], end = g_row_ptr[node + 1];
    if (beg == end) return;
    float edv = g_ed[node];
    float m = -INFINITY;
    for (int p = beg + lane; p < end; p += 32) {
        float e = tanhf(g_es[g_csr_src[p]] + edv);
        g_etmp[p] = e;
        m = fmaxf(m, e);
    }
    #pragma unroll
    for (int off = 16; off; off >>= 1) m = fmaxf(m, __shfl_xor_sync(0xffffffffu, m, off));
    float s = 0.f;
    for (int p = beg + lane; p < end; p += 32) {
        s += expf(g_etmp[p] - m);
    }
    #pragma unroll
    for (int off = 16; off; off >>= 1) s += __shfl_xor_sync(0xffffffffu, s, off);
    float inv = 1.f / s;
    for (int p = beg + lane; p < end; p += 32) {
        attn_out[g_csr_eid[p]] = expf(g_etmp[p] - m) * inv;
    }
}

// ---------------- log_softmax over 64 features: warp per node ----------------
__global__ void lsm_kernel(const float* __restrict__ feat, float* __restrict__ out) {
    int node = (blockIdx.x * blockDim.x + threadIdx.x) >> 5;
    if (node >= N_NODES) return;
    int lane = threadIdx.x & 31;
    float2 f = ((const float2*)(feat + (size_t)node * OUT_DIM))[lane];
    float m = fmaxf(f.x, f.y);
    #pragma unroll
    for (int off = 16; off; off >>= 1) m = fmaxf(m, __shfl_xor_sync(0xffffffffu, m, off));
    float s = expf(f.x - m) + expf(f.y - m);
    #pragma unroll
    for (int off = 16; off; off >>= 1) s += __shfl_xor_sync(0xffffffffu, s, off);
    float lse = m + logf(s);
    float2 o;
    o.x = f.x - lse;
    o.y = f.y - lse;
    ((float2*)(out + (size_t)node * OUT_DIM))[lane] = o;
}

// ---------------- launch ----------------
extern "C" void kernel_launch(void* const* d_in, const int* in_sizes, int n_in,
                              void* d_out, int out_size) {
    const float* h   = (const float*)d_in[0];
    const int*   src = (const int*)d_in[1];
    const int*   dst = (const int*)d_in[2];
    const float* W1  = (const float*)d_in[3];
    const float* b1  = (const float*)d_in[4];
    const float* W2  = (const float*)d_in[5];
    const float* b2  = (const float*)d_in[6];
    const float* wsr = (const float*)d_in[7];
    const float* wds = (const float*)d_in[8];
    float* out = (float*)d_out;

    float *p_hidden, *p_x0, *p_fA, *p_fB;
    cudaGetSymbolAddress((void**)&p_hidden, g_hidden);
    cudaGetSymbolAddress((void**)&p_x0, g_x0);
    cudaGetSymbolAddress((void**)&p_fA, g_fA);
    cudaGetSymbolAddress((void**)&p_fB, g_fB);

    const int TPB = 256;
    int nodeBlocks = (N_NODES + TPB - 1) / TPB;
    int edgeBlocks = (N_EDGES + TPB - 1) / TPB;
    int warpNodeBlocks = (N_NODES * 32 + TPB - 1) / TPB;

    // graph structure
    zero3_kernel<<<nodeBlocks, TPB>>>();
    count_deg_kernel<<<edgeBlocks, TPB>>>(src, dst);
    norm_kernel<<<nodeBlocks, TPB>>>();
    scan1_kernel<<<SCAN_NBLK, SCAN_BLK>>>();
    scan2_kernel<<<1, 1>>>();
    scan3_kernel<<<SCAN_NBLK, SCAN_BLK>>>();
    build_csr_kernel<<<edgeBlocks, TPB>>>(src, dst);

    // MLP: hidden = relu(h @ W1 + b1);  x0 = hidden @ W2 + b2  (tensor cores)
    {
        dim3 grid1(HID_DIM / 128, (N_NODES + 127) / 128);
        gemm_bf16x3_kernel<128, 128, 32, true><<<grid1, 256>>>(
            h, W1, b1, p_hidden, N_NODES, HID_DIM, IN_DIM);
        dim3 grid2(OUT_DIM / 64, (N_NODES + 127) / 128);
        gemm_bf16x3_kernel<128, 64, 32, false><<<grid2, 256>>>(
            p_hidden, W2, b2, p_x0, N_NODES, OUT_DIM, HID_DIM);
    }

    // K_HOPS=4 propagation, ping-pong buffers; final result in g_fB
    prop_kernel<<<warpNodeBlocks, TPB>>>(p_x0, p_fA);
    prop_kernel<<<warpNodeBlocks, TPB>>>(p_fA, p_fB);
    prop_kernel<<<warpNodeBlocks, TPB>>>(p_fB, p_fA);
    prop_kernel<<<warpNodeBlocks, TPB>>>(p_fA, p_fB);

    // attention
    dots_kernel<<<warpNodeBlocks, TPB>>>(p_fB, wsr, wds);
    attn_kernel<<<warpNodeBlocks, TPB>>>(out + (size_t)N_NODES * OUT_DIM);

    // log_softmax output
    lsm_kernel<<<warpNodeBlocks, TPB>>>(p_fB, out);
}

// round 3
// speedup vs baseline: 1.7344x; 1.0155x over previous
#include <cuda_runtime.h>
#include <cuda_bf16.h>
#include <math.h>
#include <stdint.h>

#define N_NODES 50000
#define N_EDGES 1600000
#define IN_DIM 512
#define HID_DIM 256
#define OUT_DIM 64
#define K_HOPS 4
#define ALPHA 0.1f

#define SCAN_BLK 1024
#define SCAN_NBLK ((N_NODES + SCAN_BLK - 1) / SCAN_BLK)   // 49

// ---------------- device scratch (no allocs allowed) ----------------
__device__ float g_hidden[(size_t)N_NODES * HID_DIM];
__device__ float g_x0[(size_t)N_NODES * OUT_DIM];
__device__ float g_fA[(size_t)N_NODES * OUT_DIM];
__device__ float g_fB[(size_t)N_NODES * OUT_DIM];
__device__ int   g_deg_out[N_NODES];
__device__ int   g_deg_in[N_NODES];
__device__ int   g_fill[N_NODES];
__device__ int   g_row_ptr[N_NODES + 1];
__device__ float g_nsrc[N_NODES];
__device__ float g_ndst[N_NODES];
__device__ int   g_csr_src[N_EDGES];
__device__ int   g_csr_eid[N_EDGES];
__device__ float g_es[N_NODES];
__device__ float g_ed[N_NODES];
__device__ float g_etmp[N_EDGES];
__device__ int   g_bsum[SCAN_NBLK];
__device__ int   g_boff[SCAN_NBLK];

// ---------------- small kernels ----------------
__global__ void zero3_kernel() {
    int i = blockIdx.x * blockDim.x + threadIdx.x;
    if (i < N_NODES) {
        g_deg_out[i] = 0;
        g_deg_in[i]  = 0;
        g_fill[i]    = 0;
    }
}

__global__ void count_deg_kernel(const int* __restrict__ src, const int* __restrict__ dst) {
    int e = blockIdx.x * blockDim.x + threadIdx.x;
    if (e < N_EDGES) {
        atomicAdd(&g_deg_out[src[e]], 1);
        atomicAdd(&g_deg_in[dst[e]], 1);
    }
}

__global__ void norm_kernel() {
    int i = blockIdx.x * blockDim.x + threadIdx.x;
    if (i < N_NODES) {
        int doo = g_deg_out[i]; if (doo < 1) doo = 1;
        int din = g_deg_in[i];  if (din < 1) din = 1;
        g_nsrc[i] = rsqrtf((float)doo);
        g_ndst[i] = rsqrtf((float)din);
    }
}

// ---- 3-phase grid-wide exclusive scan of g_deg_in -> g_row_ptr ----
__global__ void scan1_kernel() {
    __shared__ int warpsum[32];
    int tid = threadIdx.x, lane = tid & 31, wid = tid >> 5;
    int i = blockIdx.x * SCAN_BLK + tid;
    int v = (i < N_NODES) ? g_deg_in[i] : 0;
    int x = v;
    #pragma unroll
    for (int off = 1; off < 32; off <<= 1) {
        int t = __shfl_up_sync(0xffffffffu, x, off);
        if (lane >= off) x += t;
    }
    if (lane == 31) warpsum[wid] = x;
    __syncthreads();
    if (wid == 0) {
        int w = warpsum[lane];
        #pragma unroll
        for (int off = 1; off < 32; off <<= 1) {
            int t = __shfl_up_sync(0xffffffffu, w, off);
            if (lane >= off) w += t;
        }
        warpsum[lane] = w;
    }
    __syncthreads();
    int offset = (wid > 0) ? warpsum[wid - 1] : 0;
    if (i < N_NODES) g_row_ptr[i] = x + offset - v;
    if (tid == SCAN_BLK - 1) g_bsum[blockIdx.x] = x + offset;
}

__global__ void scan2_kernel() {
    int run = 0;
    for (int i = 0; i < SCAN_NBLK; i++) {
        g_boff[i] = run;
        run += g_bsum[i];
    }
    g_row_ptr[N_NODES] = run;
}

__global__ void scan3_kernel() {
    int i = blockIdx.x * SCAN_BLK + threadIdx.x;
    if (i < N_NODES && blockIdx.x > 0) g_row_ptr[i] += g_boff[blockIdx.x];
}

__global__ void build_csr_kernel(const int* __restrict__ src, const int* __restrict__ dst) {
    int e = blockIdx.x * blockDim.x + threadIdx.x;
    if (e < N_EDGES) {
        int d = dst[e];
        int pos = g_row_ptr[d] + atomicAdd(&g_fill[d], 1);
        g_csr_src[pos] = src[e];
        g_csr_eid[pos] = e;
    }
}

// ---------------- tensor-core GEMM, double-buffered, bf16 3-split ----------
__device__ __forceinline__ uint32_t smem_u32(const void* p) {
    return (uint32_t)__cvta_generic_to_shared(p);
}
__device__ __forceinline__ void ldsm_x4(uint32_t* r, uint32_t addr) {
    asm volatile("ldmatrix.sync.aligned.m8n8.x4.shared.b16 {%0,%1,%2,%3}, [%4];\n"
        : "=r"(r[0]), "=r"(r[1]), "=r"(r[2]), "=r"(r[3]) : "r"(addr));
}
__device__ __forceinline__ void ldsm_x4_trans(uint32_t* r, uint32_t addr) {
    asm volatile("ldmatrix.sync.aligned.m8n8.x4.trans.shared.b16 {%0,%1,%2,%3}, [%4];\n"
        : "=r"(r[0]), "=r"(r[1]), "=r"(r[2]), "=r"(r[3]) : "r"(addr));
}
__device__ __forceinline__ void mma16816(float* c, const uint32_t* a, const uint32_t* b) {
    asm volatile(
        "mma.sync.aligned.m16n8k16.row.col.f32.bf16.bf16.f32 "
        "{%0,%1,%2,%3}, {%4,%5,%6,%7}, {%8,%9}, {%0,%1,%2,%3};\n"
        : "+f"(c[0]), "+f"(c[1]), "+f"(c[2]), "+f"(c[3])
        : "r"(a[0]), "r"(a[1]), "r"(a[2]), "r"(a[3]), "r"(b[0]), "r"(b[1]));
}
__device__ __forceinline__ void split2(float x, float y, uint32_t& hi, uint32_t& lo) {
    __nv_bfloat16 hx = __float2bfloat16(x);
    __nv_bfloat16 hy = __float2bfloat16(y);
    __nv_bfloat16 lx = __float2bfloat16(x - __bfloat162float(hx));
    __nv_bfloat16 ly = __float2bfloat16(y - __bfloat162float(hy));
    __nv_bfloat162 h2; h2.x = hx; h2.y = hy;
    __nv_bfloat162 l2; l2.x = lx; l2.y = ly;
    hi = *(uint32_t*)&h2;
    lo = *(uint32_t*)&l2;
}

// BM=128, BK=16, 256 threads, 8 warps (4x2). BN in {64,128}.
template <int BN, bool RELU>
__global__ __launch_bounds__(256)
void gemm_bf16x3_kernel(const float* __restrict__ A, const float* __restrict__ B,
                        const float* __restrict__ bias, float* __restrict__ C,
                        int M, int N, int K) {
    constexpr int BM = 128, BK = 16;
    constexpr int WN  = BN / 2;
    constexpr int NJ  = WN / 8;
    constexpr int NJP = NJ / 2;
    constexpr int NLA = BM * BK / 1024;   // float4 A loads / thread (=2)
    constexpr int NLB = BK * BN / 1024;   // float4 B loads / thread (1 or 2)
    __shared__ __align__(16) __nv_bfloat16 As_hi[2][BM][BK + 8];
    __shared__ __align__(16) __nv_bfloat16 As_lo[2][BM][BK + 8];
    __shared__ __align__(16) __nv_bfloat16 Bs_hi[2][BK][BN + 8];
    __shared__ __align__(16) __nv_bfloat16 Bs_lo[2][BK][BN + 8];

    int tid = threadIdx.x;
    int lane = tid & 31, wid = tid >> 5;
    int wm = wid & 3, wn = wid >> 2;
    int rowBase = blockIdx.y * BM;
    int colBase = blockIdx.x * BN;

    float acc[2][NJ][4];
    #pragma unroll
    for (int i = 0; i < 2; i++)
        #pragma unroll
        for (int j = 0; j < NJ; j++)
            #pragma unroll
            for (int q = 0; q < 4; q++) acc[i][j][q] = 0.f;

    float4 pa[NLA], pb[NLB];

    auto load_tiles = [&](int k0) {
        #pragma unroll
        for (int j = 0; j < NLA; j++) {
            int i = tid + j * 256;
            int r = i >> 2;               // BK/4 == 4
            int c4 = (i & 3) << 2;
            int grow = rowBase + r;
            pa[j] = make_float4(0.f, 0.f, 0.f, 0.f);
            if (grow < M) pa[j] = *(const float4*)&A[(size_t)grow * K + k0 + c4];
        }
        #pragma unroll
        for (int j = 0; j < NLB; j++) {
            int i = tid + j * 256;
            int r = i / (BN / 4);
            int c4 = (i % (BN / 4)) << 2;
            pb[j] = *(const float4*)&B[(size_t)(k0 + r) * N + colBase + c4];
        }
    };
    auto store_tiles = [&](int buf) {
        #pragma unroll
        for (int j = 0; j < NLA; j++) {
            int i = tid + j * 256;
            int r = i >> 2;
            int c4 = (i & 3) << 2;
            uint32_t h0, l0, h1, l1;
            split2(pa[j].x, pa[j].y, h0, l0);
            split2(pa[j].z, pa[j].w, h1, l1);
            *(uint32_t*)&As_hi[buf][r][c4]     = h0;
            *(uint32_t*)&As_hi[buf][r][c4 + 2] = h1;
            *(uint32_t*)&As_lo[buf][r][c4]     = l0;
            *(uint32_t*)&As_lo[buf][r][c4 + 2] = l1;
        }
        #pragma unroll
        for (int j = 0; j < NLB; j++) {
            int i = tid + j * 256;
            int r = i / (BN / 4);
            int c4 = (i % (BN / 4)) << 2;
            uint32_t h0, l0, h1, l1;
            split2(pb[j].x, pb[j].y, h0, l0);
            split2(pb[j].z, pb[j].w, h1, l1);
            *(uint32_t*)&Bs_hi[buf][r][c4]     = h0;
            *(uint32_t*)&Bs_hi[buf][r][c4 + 2] = h1;
            *(uint32_t*)&Bs_lo[buf][r][c4]     = l0;
            *(uint32_t*)&Bs_lo[buf][r][c4 + 2] = l1;
        }
    };

    int T = K / BK;
    load_tiles(0);
    store_tiles(0);
    __syncthreads();
    int cur = 0;

    for (int t = 0; t < T; t++) {
        if (t + 1 < T) load_tiles((t + 1) * BK);   // LDG overlaps MMA below

        uint32_t a_hi[2][4], a_lo[2][4];
        #pragma unroll
        for (int mi = 0; mi < 2; mi++) {
            int r = wm * 32 + mi * 16 + (lane & 15);
            int c = (lane >> 4) << 3;
            ldsm_x4(a_hi[mi], smem_u32(&As_hi[cur][r][c]));
            ldsm_x4(a_lo[mi], smem_u32(&As_lo[cur][r][c]));
        }
        uint32_t b_hi[NJ][2], b_lo[NJ][2];
        #pragma unroll
        for (int p = 0; p < NJP; p++) {
            int r = (lane & 7) + (lane & 8);
            int c = wn * WN + p * 16 + ((lane >> 4) << 3);
            uint32_t tt[4];
            ldsm_x4_trans(tt, smem_u32(&Bs_hi[cur][r][c]));
            b_hi[2 * p][0] = tt[0]; b_hi[2 * p][1] = tt[1];
            b_hi[2 * p + 1][0] = tt[2]; b_hi[2 * p + 1][1] = tt[3];
            ldsm_x4_trans(tt, smem_u32(&Bs_lo[cur][r][c]));
            b_lo[2 * p][0] = tt[0]; b_lo[2 * p][1] = tt[1];
            b_lo[2 * p + 1][0] = tt[2]; b_lo[2 * p + 1][1] = tt[3];
        }
        #pragma unroll
        for (int mi = 0; mi < 2; mi++)
            #pragma unroll
            for (int nj = 0; nj < NJ; nj++) {
                mma16816(acc[mi][nj], a_hi[mi], b_hi[nj]);
                mma16816(acc[mi][nj], a_hi[mi], b_lo[nj]);
                mma16816(acc[mi][nj], a_lo[mi], b_hi[nj]);
            }

        if (t + 1 < T) {
            store_tiles(cur ^ 1);
            __syncthreads();
            cur ^= 1;
        }
    }

    // epilogue
    int g = lane >> 2, tig = lane & 3;
    #pragma unroll
    for (int mi = 0; mi < 2; mi++) {
        int row0 = rowBase + wm * 32 + mi * 16 + g;
        int row1 = row0 + 8;
        #pragma unroll
        for (int nj = 0; nj < NJ; nj++) {
            int col = colBase + wn * WN + nj * 8 + 2 * tig;
            float bv0 = bias[col], bv1 = bias[col + 1];
            if (row0 < M) {
                float v0 = acc[mi][nj][0] + bv0;
                float v1 = acc[mi][nj][1] + bv1;
                if (RELU) { v0 = fmaxf(v0, 0.f); v1 = fmaxf(v1, 0.f); }
                C[(size_t)row0 * N + col]     = v0;
                C[(size_t)row0 * N + col + 1] = v1;
            }
            if (row1 < M) {
                float v2 = acc[mi][nj][2] + bv0;
                float v3 = acc[mi][nj][3] + bv1;
                if (RELU) { v2 = fmaxf(v2, 0.f); v3 = fmaxf(v3, 0.f); }
                C[(size_t)row1 * N + col]     = v2;
                C[(size_t)row1 * N + col + 1] = v3;
            }
        }
    }
}

// ---------------- propagation hop: half-warp per node, float4/lane --------
__global__ void prop_kernel(const float* __restrict__ fin, float* __restrict__ fout) {
    int node = (blockIdx.x * blockDim.x + threadIdx.x) >> 4;
    if (node >= N_NODES) return;
    int lane = threadIdx.x & 15;
    int beg = g_row_ptr[node], end = g_row_ptr[node + 1];
    float4 a = make_float4(0.f, 0.f, 0.f, 0.f);
    int p = beg;
    for (; p + 2 <= end; p += 2) {
        int s0 = g_csr_src[p];
        int s1 = g_csr_src[p + 1];
        float ns0 = g_nsrc[s0];
        float ns1 = g_nsrc[s1];
        float4 v0 = ((const float4*)(fin + (size_t)s0 * OUT_DIM))[lane];
        float4 v1 = ((const float4*)(fin + (size_t)s1 * OUT_DIM))[lane];
        a.x += v0.x * ns0 + v1.x * ns1;
        a.y += v0.y * ns0 + v1.y * ns1;
        a.z += v0.z * ns0 + v1.z * ns1;
        a.w += v0.w * ns0 + v1.w * ns1;
    }
    if (p < end) {
        int s = g_csr_src[p];
        float ns = g_nsrc[s];
        float4 v = ((const float4*)(fin + (size_t)s * OUT_DIM))[lane];
        a.x += v.x * ns; a.y += v.y * ns; a.z += v.z * ns; a.w += v.w * ns;
    }
    float nd = (1.f - ALPHA) * g_ndst[node];
    float4 z = ((const float4*)(g_x0 + (size_t)node * OUT_DIM))[lane];
    float4 o;
    o.x = a.x * nd + ALPHA * z.x;
    o.y = a.y * nd + ALPHA * z.y;
    o.z = a.z * nd + ALPHA * z.z;
    o.w = a.w * nd + ALPHA * z.w;
    ((float4*)(fout + (size_t)node * OUT_DIM))[lane] = o;
}

// ---------------- attention score dots: warp per node ----------------
__global__ void dots_kernel(const float* __restrict__ feat,
                            const float* __restrict__ wsrc,
                            const float* __restrict__ wdst) {
    int node = (blockIdx.x * blockDim.x + threadIdx.x) >> 5;
    if (node >= N_NODES) return;
    int lane = threadIdx.x & 31;
    float2 f = ((const float2*)(feat + (size_t)node * OUT_DIM))[lane];
    float2 a = ((const float2*)wsrc)[lane];
    float2 b = ((const float2*)wdst)[lane];
    float s = f.x * a.x + f.y * a.y;
    float d = f.x * b.x + f.y * b.y;
    #pragma unroll
    for (int off = 16; off; off >>= 1) {
        s += __shfl_xor_sync(0xffffffffu, s, off);
        d += __shfl_xor_sync(0xffffffffu, d, off);
    }
    if (lane == 0) {
        g_es[node] = s;
        g_ed[node] = d;
    }
}

// ---------------- attention softmax over in-edges: warp per node ----------
__global__ void attn_kernel(float* __restrict__ attn_out) {
    int node = (blockIdx.x * blockDim.x + threadIdx.x) >> 5;
    if (node >= N_NODES) return;
    int lane = threadIdx.x & 31;
    int beg = g_row_ptr[node], end = g_row_ptr[node + 1];
    int deg = end - beg;
    if (deg == 0) return;
    float edv = g_ed[node];

    if (deg <= 32) {
        // single pass: edge value lives in a register
        int p = beg + lane;
        bool act = p < end;
        float e = act ? tanhf(g_es[g_csr_src[p]] + edv) : -INFINITY;
        float m = e;
        #pragma unroll
        for (int off = 16; off; off >>= 1) m = fmaxf(m, __shfl_xor_sync(0xffffffffu, m, off));
        float ex = act ? expf(e - m) : 0.f;
        float s = ex;
        #pragma unroll
        for (int off = 16; off; off >>= 1) s += __shfl_xor_sync(0xffffffffu, s, off);
        if (act) attn_out[g_csr_eid[p]] = ex / s;
        return;
    }

    float m = -INFINITY;
    for (int p = beg + lane; p < end; p += 32) {
        float e = tanhf(g_es[g_csr_src[p]] + edv);
        g_etmp[p] = e;
        m = fmaxf(m, e);
    }
    #pragma unroll
    for (int off = 16; off; off >>= 1) m = fmaxf(m, __shfl_xor_sync(0xffffffffu, m, off));
    float s = 0.f;
    for (int p = beg + lane; p < end; p += 32) {
        float ex = expf(g_etmp[p] - m);
        g_etmp[p] = ex;          // cache exp for pass 3
        s += ex;
    }
    #pragma unroll
    for (int off = 16; off; off >>= 1) s += __shfl_xor_sync(0xffffffffu, s, off);
    float inv = 1.f / s;
    for (int p = beg + lane; p < end; p += 32) {
        attn_out[g_csr_eid[p]] = g_etmp[p] * inv;
    }
}

// ---------------- log_softmax over 64 features: warp per node -------------
__global__ void lsm_kernel(const float* __restrict__ feat, float* __restrict__ out) {
    int node = (blockIdx.x * blockDim.x + threadIdx.x) >> 5;
    if (node >= N_NODES) return;
    int lane = threadIdx.x & 31;
    float2 f = ((const float2*)(feat + (size_t)node * OUT_DIM))[lane];
    float m = fmaxf(f.x, f.y);
    #pragma unroll
    for (int off = 16; off; off >>= 1) m = fmaxf(m, __shfl_xor_sync(0xffffffffu, m, off));
    float s = expf(f.x - m) + expf(f.y - m);
    #pragma unroll
    for (int off = 16; off; off >>= 1) s += __shfl_xor_sync(0xffffffffu, s, off);
    float lse = m + logf(s);
    float2 o;
    o.x = f.x - lse;
    o.y = f.y - lse;
    ((float2*)(out + (size_t)node * OUT_DIM))[lane] = o;
}

// ---------------- launch ----------------
extern "C" void kernel_launch(void* const* d_in, const int* in_sizes, int n_in,
                              void* d_out, int out_size) {
    const float* h   = (const float*)d_in[0];
    const int*   src = (const int*)d_in[1];
    const int*   dst = (const int*)d_in[2];
    const float* W1  = (const float*)d_in[3];
    const float* b1  = (const float*)d_in[4];
    const float* W2  = (const float*)d_in[5];
    const float* b2  = (const float*)d_in[6];
    const float* wsr = (const float*)d_in[7];
    const float* wds = (const float*)d_in[8];
    float* out = (float*)d_out;

    float *p_hidden, *p_x0, *p_fA, *p_fB;
    cudaGetSymbolAddress((void**)&p_hidden, g_hidden);
    cudaGetSymbolAddress((void**)&p_x0, g_x0);
    cudaGetSymbolAddress((void**)&p_fA, g_fA);
    cudaGetSymbolAddress((void**)&p_fB, g_fB);

    const int TPB = 256;
    int nodeBlocks = (N_NODES + TPB - 1) / TPB;
    int edgeBlocks = (N_EDGES + TPB - 1) / TPB;
    int warpNodeBlocks = (N_NODES * 32 + TPB - 1) / TPB;
    int hwNodeBlocks = (N_NODES * 16 + TPB - 1) / TPB;

    // graph structure + MLP interleaved (gemm1 placed 4th for ncu capture slot)
    zero3_kernel<<<nodeBlocks, TPB>>>();
    count_deg_kernel<<<edgeBlocks, TPB>>>(src, dst);
    norm_kernel<<<nodeBlocks, TPB>>>();

    dim3 grid1(HID_DIM / 128, (N_NODES + 127) / 128);
    gemm_bf16x3_kernel<128, true><<<grid1, 256>>>(h, W1, b1, p_hidden,
                                                  N_NODES, HID_DIM, IN_DIM);

    scan1_kernel<<<SCAN_NBLK, SCAN_BLK>>>();
    scan2_kernel<<<1, 1>>>();
    scan3_kernel<<<SCAN_NBLK, SCAN_BLK>>>();
    build_csr_kernel<<<edgeBlocks, TPB>>>(src, dst);

    dim3 grid2(OUT_DIM / 64, (N_NODES + 127) / 128);
    gemm_bf16x3_kernel<64, false><<<grid2, 256>>>(p_hidden, W2, b2, p_x0,
                                                  N_NODES, OUT_DIM, HID_DIM);

    // K_HOPS=4 propagation, ping-pong buffers; final result in g_fB
    prop_kernel<<<hwNodeBlocks, TPB>>>(p_x0, p_fA);
    prop_kernel<<<hwNodeBlocks, TPB>>>(p_fA, p_fB);
    prop_kernel<<<hwNodeBlocks, TPB>>>(p_fB, p_fA);
    prop_kernel<<<hwNodeBlocks, TPB>>>(p_fA, p_fB);

    // attention
    dots_kernel<<<warpNodeBlocks, TPB>>>(p_fB, wsr, wds);
    attn_kernel<<<warpNodeBlocks, TPB>>>(out + (size_t)N_NODES * OUT_DIM);

    // log_softmax output
    lsm_kernel<<<warpNodeBlocks, TPB>>>(p_fB, out);
}

// round 6
// speedup vs baseline: 1.8183x; 1.0484x over previous
#include <cuda_runtime.h>
#include <cuda_bf16.h>
#include <cuda_fp16.h>
#include <math.h>
#include <stdint.h>

#define N_NODES 50000
#define N_EDGES 1600000
#define IN_DIM 512
#define HID_DIM 256
#define OUT_DIM 64
#define K_HOPS 4
#define ALPHA 0.1f

#define SCAN_BLK 1024
#define SCAN_NBLK ((N_NODES + SCAN_BLK - 1) / SCAN_BLK)   // 49

// ---------------- device scratch (no allocs allowed) ----------------
__device__ __half  g_h16[(size_t)N_NODES * IN_DIM];
__device__ __half  g_w1h[IN_DIM * HID_DIM];
__device__ __half  g_w1l[IN_DIM * HID_DIM];
__device__ __half  g_w2h[HID_DIM * OUT_DIM];
__device__ __half  g_w2l[HID_DIM * OUT_DIM];
__device__ __half  g_hid16[(size_t)N_NODES * HID_DIM];
__device__ float g_x0[(size_t)N_NODES * OUT_DIM];
__device__ float g_fA[(size_t)N_NODES * OUT_DIM];
__device__ float g_fB[(size_t)N_NODES * OUT_DIM];
__device__ int   g_deg_out[N_NODES];
__device__ int   g_deg_in[N_NODES];
__device__ int   g_fill[N_NODES];
__device__ int   g_row_ptr[N_NODES + 1];
__device__ float g_nsrc[N_NODES];
__device__ float g_ndst[N_NODES];
__device__ int   g_csr_src[N_EDGES];
__device__ int   g_csr_eid[N_EDGES];
__device__ float g_es[N_NODES];
__device__ float g_ed[N_NODES];
__device__ float g_etmp[N_EDGES];
__device__ int   g_bsum[SCAN_NBLK];
__device__ int   g_boff[SCAN_NBLK];

// ---------------- conversion kernels ----------------
__global__ void f32_to_f16_kernel(const float* __restrict__ in,
                                  __half* __restrict__ out, int n4) {
    int i = blockIdx.x * blockDim.x + threadIdx.x;
    if (i < n4) {
        float4 v = ((const float4*)in)[i];
        __half2 a = __floats2half2_rn(v.x, v.y);
        __half2 b = __floats2half2_rn(v.z, v.w);
        uint2 u;
        u.x = *(uint32_t*)&a;
        u.y = *(uint32_t*)&b;
        ((uint2*)out)[i] = u;
    }
}

__global__ void f32_split_f16_kernel(const float* __restrict__ in,
                                     __half* __restrict__ hi,
                                     __half* __restrict__ lo, int n4) {
    int i = blockIdx.x * blockDim.x + threadIdx.x;
    if (i < n4) {
        float4 v = ((const float4*)in)[i];
        __half hx = __float2half_rn(v.x), hy = __float2half_rn(v.y);
        __half hz = __float2half_rn(v.z), hw = __float2half_rn(v.w);
        __half lx = __float2half_rn(v.x - __half2float(hx));
        __half ly = __float2half_rn(v.y - __half2float(hy));
        __half lz = __float2half_rn(v.z - __half2float(hz));
        __half lw = __float2half_rn(v.w - __half2float(hw));
        __half2 h0; h0.x = hx; h0.y = hy;
        __half2 h1; h1.x = hz; h1.y = hw;
        __half2 l0; l0.x = lx; l0.y = ly;
        __half2 l1; l1.x = lz; l1.y = lw;
        uint2 uh, ul;
        uh.x = *(uint32_t*)&h0; uh.y = *(uint32_t*)&h1;
        ul.x = *(uint32_t*)&l0; ul.y = *(uint32_t*)&l1;
        ((uint2*)hi)[i] = uh;
        ((uint2*)lo)[i] = ul;
    }
}

// ---------------- small kernels ----------------
__global__ void zero3_kernel() {
    int i = blockIdx.x * blockDim.x + threadIdx.x;
    if (i < N_NODES) {
        g_deg_out[i] = 0;
        g_deg_in[i]  = 0;
        g_fill[i]    = 0;
    }
}

__global__ void count_deg_kernel(const int* __restrict__ src, const int* __restrict__ dst) {
    int e = blockIdx.x * blockDim.x + threadIdx.x;
    if (e < N_EDGES) {
        atomicAdd(&g_deg_out[src[e]], 1);
        atomicAdd(&g_deg_in[dst[e]], 1);
    }
}

__global__ void norm_kernel() {
    int i = blockIdx.x * blockDim.x + threadIdx.x;
    if (i < N_NODES) {
        int doo = g_deg_out[i]; if (doo < 1) doo = 1;
        int din = g_deg_in[i];  if (din < 1) din = 1;
        g_nsrc[i] = rsqrtf((float)doo);
        g_ndst[i] = rsqrtf((float)din);
    }
}

// ---- 3-phase grid-wide exclusive scan of g_deg_in -> g_row_ptr ----
__global__ void scan1_kernel() {
    __shared__ int warpsum[32];
    int tid = threadIdx.x, lane = tid & 31, wid = tid >> 5;
    int i = blockIdx.x * SCAN_BLK + tid;
    int v = (i < N_NODES) ? g_deg_in[i] : 0;
    int x = v;
    #pragma unroll
    for (int off = 1; off < 32; off <<= 1) {
        int t = __shfl_up_sync(0xffffffffu, x, off);
        if (lane >= off) x += t;
    }
    if (lane == 31) warpsum[wid] = x;
    __syncthreads();
    if (wid == 0) {
        int w = warpsum[lane];
        #pragma unroll
        for (int off = 1; off < 32; off <<= 1) {
            int t = __shfl_up_sync(0xffffffffu, w, off);
            if (lane >= off) w += t;
        }
        warpsum[lane] = w;
    }
    __syncthreads();
    int offset = (wid > 0) ? warpsum[wid - 1] : 0;
    if (i < N_NODES) g_row_ptr[i] = x + offset - v;
    if (tid == SCAN_BLK - 1) g_bsum[blockIdx.x] = x + offset;
}

__global__ void scan2_kernel() {
    int run = 0;
    for (int i = 0; i < SCAN_NBLK; i++) {
        g_boff[i] = run;
        run += g_bsum[i];
    }
    g_row_ptr[N_NODES] = run;
}

__global__ void scan3_kernel() {
    int i = blockIdx.x * SCAN_BLK + threadIdx.x;
    if (i < N_NODES && blockIdx.x > 0) g_row_ptr[i] += g_boff[blockIdx.x];
}

__global__ void build_csr_kernel(const int* __restrict__ src, const int* __restrict__ dst) {
    int e = blockIdx.x * blockDim.x + threadIdx.x;
    if (e < N_EDGES) {
        int d = dst[e];
        int pos = g_row_ptr[d] + atomicAdd(&g_fill[d], 1);
        g_csr_src[pos] = src[e];
        g_csr_eid[pos] = e;
    }
}

// ---------------- fp16 tensor-core GEMM, static smem, cp.async pipeline --
__device__ __forceinline__ uint32_t smem_u32(const void* p) {
    return (uint32_t)__cvta_generic_to_shared(p);
}
__device__ __forceinline__ void cp_async16(uint32_t s, const void* g) {
    asm volatile("cp.async.cg.shared.global [%0], [%1], 16;\n"
        :: "r"(s), "l"(__cvta_generic_to_global(g)));
}
__device__ __forceinline__ void cp_commit() {
    asm volatile("cp.async.commit_group;\n");
}
template <int NW>
__device__ __forceinline__ void cp_wait() {
    asm volatile("cp.async.wait_group %0;\n" :: "n"(NW));
}
__device__ __forceinline__ void ldsm_x4(uint32_t* r, uint32_t addr) {
    asm volatile("ldmatrix.sync.aligned.m8n8.x4.shared.b16 {%0,%1,%2,%3}, [%4];\n"
        : "=r"(r[0]), "=r"(r[1]), "=r"(r[2]), "=r"(r[3]) : "r"(addr));
}
__device__ __forceinline__ void ldsm_x4_trans(uint32_t* r, uint32_t addr) {
    asm volatile("ldmatrix.sync.aligned.m8n8.x4.trans.shared.b16 {%0,%1,%2,%3}, [%4];\n"
        : "=r"(r[0]), "=r"(r[1]), "=r"(r[2]), "=r"(r[3]) : "r"(addr));
}
__device__ __forceinline__ void mma16816h(float* c, const uint32_t* a, const uint32_t* b) {
    asm volatile(
        "mma.sync.aligned.m16n8k16.row.col.f32.f16.f16.f32 "
        "{%0,%1,%2,%3}, {%4,%5,%6,%7}, {%8,%9}, {%0,%1,%2,%3};\n"
        : "+f"(c[0]), "+f"(c[1]), "+f"(c[2]), "+f"(c[3])
        : "r"(a[0]), "r"(a[1]), "r"(a[2]), "r"(a[3]), "r"(b[0]), "r"(b[1]));
}

#define GBM 128
#define GBK 16
#define GSTAGES 3

// C = A(fp16) @ (Bhi+Blo) + bias; static smem: 44.5KB (BN=128) / 32KB (BN=64)
template <int BN, bool RELU, bool OUT16>
__global__ __launch_bounds__(256)
void gemm_f16_kernel(const __half* __restrict__ A,
                     const __half* __restrict__ Bh,
                     const __half* __restrict__ Bl,
                     const float* __restrict__ bias,
                     float* __restrict__ Cf,
                     __half* __restrict__ C16,
                     int M, int N, int K) {
    constexpr int WN  = BN / 2;
    constexpr int NJ  = WN / 8;
    constexpr int NJP = NJ / 2;
    __shared__ __align__(16) __half As[GSTAGES][GBM][GBK + 8];
    __shared__ __align__(16) __half Bhs[GSTAGES][GBK][BN + 8];
    __shared__ __align__(16) __half Bls[GSTAGES][GBK][BN + 8];

    int tid = threadIdx.x;
    int lane = tid & 31, wid = tid >> 5;
    int wm = wid & 3, wn = wid >> 2;
    int rowBase = blockIdx.y * GBM;
    int colBase = blockIdx.x * BN;

    float acc[2][NJ][4];
    #pragma unroll
    for (int i = 0; i < 2; i++)
        #pragma unroll
        for (int j = 0; j < NJ; j++)
            #pragma unroll
            for (int q = 0; q < 4; q++) acc[i][j][q] = 0.f;

    auto load_stage = [&](int s, int k0) {
        // A: 128x16 halves = 256 16B-chunks (1/thread)
        {
            int q = tid;
            int r = q >> 1;
            int c8 = (q & 1) << 3;
            int row = rowBase + r;
            if (row > M - 1) row = M - 1;
            cp_async16(smem_u32(&As[s][r][c8]), A + (size_t)row * K + k0 + c8);
        }
        // B: 16xBN halves = 2*BN chunks per array
        #pragma unroll
        for (int q = tid; q < 2 * BN; q += 256) {
            int r = q / (BN / 8);
            int c8 = (q % (BN / 8)) << 3;
            const size_t off = (size_t)(k0 + r) * N + colBase + c8;
            cp_async16(smem_u32(&Bhs[s][r][c8]), Bh + off);
            cp_async16(smem_u32(&Bls[s][r][c8]), Bl + off);
        }
        cp_commit();
    };

    int T = K / GBK;
    load_stage(0, 0);
    load_stage(1, GBK);

    for (int t = 0; t < T; t++) {
        cp_wait<GSTAGES - 2>();
        __syncthreads();
        int pf = t + GSTAGES - 1;
        if (pf < T) load_stage(pf % GSTAGES, pf * GBK);
        int cur = t % GSTAGES;

        uint32_t a[2][4];
        #pragma unroll
        for (int mi = 0; mi < 2; mi++) {
            int r = wm * 32 + mi * 16 + (lane & 15);
            int c = (lane >> 4) << 3;
            ldsm_x4(a[mi], smem_u32(&As[cur][r][c]));
        }
        uint32_t bh[NJ][2], bl[NJ][2];
        #pragma unroll
        for (int p = 0; p < NJP; p++) {
            int r = (lane & 7) + (lane & 8);
            int c = wn * WN + p * 16 + ((lane >> 4) << 3);
            uint32_t tt[4];
            ldsm_x4_trans(tt, smem_u32(&Bhs[cur][r][c]));
            bh[2 * p][0] = tt[0]; bh[2 * p][1] = tt[1];
            bh[2 * p + 1][0] = tt[2]; bh[2 * p + 1][1] = tt[3];
            ldsm_x4_trans(tt, smem_u32(&Bls[cur][r][c]));
            bl[2 * p][0] = tt[0]; bl[2 * p][1] = tt[1];
            bl[2 * p + 1][0] = tt[2]; bl[2 * p + 1][1] = tt[3];
        }
        #pragma unroll
        for (int mi = 0; mi < 2; mi++)
            #pragma unroll
            for (int nj = 0; nj < NJ; nj++) {
                mma16816h(acc[mi][nj], a[mi], bh[nj]);
                mma16816h(acc[mi][nj], a[mi], bl[nj]);
            }
        __syncthreads();
    }

    // epilogue
    int g = lane >> 2, tig = lane & 3;
    #pragma unroll
    for (int mi = 0; mi < 2; mi++) {
        int row0 = rowBase + wm * 32 + mi * 16 + g;
        int row1 = row0 + 8;
        #pragma unroll
        for (int nj = 0; nj < NJ; nj++) {
            int col = colBase + wn * WN + nj * 8 + 2 * tig;
            float bv0 = bias[col], bv1 = bias[col + 1];
            float v0 = acc[mi][nj][0] + bv0;
            float v1 = acc[mi][nj][1] + bv1;
            float v2 = acc[mi][nj][2] + bv0;
            float v3 = acc[mi][nj][3] + bv1;
            if (RELU) {
                v0 = fmaxf(v0, 0.f); v1 = fmaxf(v1, 0.f);
                v2 = fmaxf(v2, 0.f); v3 = fmaxf(v3, 0.f);
            }
            if (OUT16) {
                if (row0 < M) *(__half2*)&C16[(size_t)row0 * N + col] = __floats2half2_rn(v0, v1);
                if (row1 < M) *(__half2*)&C16[(size_t)row1 * N + col] = __floats2half2_rn(v2, v3);
            } else {
                if (row0 < M) {
                    Cf[(size_t)row0 * N + col]     = v0;
                    Cf[(size_t)row0 * N + col + 1] = v1;
                }
                if (row1 < M) {
                    Cf[(size_t)row1 * N + col]     = v2;
                    Cf[(size_t)row1 * N + col + 1] = v3;
                }
            }
        }
    }
}

// ---------------- propagation hop: half-warp per node, float4/lane --------
__global__ void prop_kernel(const float* __restrict__ fin, float* __restrict__ fout) {
    int node = (blockIdx.x * blockDim.x + threadIdx.x) >> 4;
    if (node >= N_NODES) return;
    int lane = threadIdx.x & 15;
    int beg = g_row_ptr[node], end = g_row_ptr[node + 1];
    float4 a = make_float4(0.f, 0.f, 0.f, 0.f);
    int p = beg;
    for (; p + 2 <= end; p += 2) {
        int s0 = g_csr_src[p];
        int s1 = g_csr_src[p + 1];
        float ns0 = g_nsrc[s0];
        float ns1 = g_nsrc[s1];
        float4 v0 = ((const float4*)(fin + (size_t)s0 * OUT_DIM))[lane];
        float4 v1 = ((const float4*)(fin + (size_t)s1 * OUT_DIM))[lane];
        a.x += v0.x * ns0 + v1.x * ns1;
        a.y += v0.y * ns0 + v1.y * ns1;
        a.z += v0.z * ns0 + v1.z * ns1;
        a.w += v0.w * ns0 + v1.w * ns1;
    }
    if (p < end) {
        int s = g_csr_src[p];
        float ns = g_nsrc[s];
        float4 v = ((const float4*)(fin + (size_t)s * OUT_DIM))[lane];
        a.x += v.x * ns; a.y += v.y * ns; a.z += v.z * ns; a.w += v.w * ns;
    }
    float nd = (1.f - ALPHA) * g_ndst[node];
    float4 z = ((const float4*)(g_x0 + (size_t)node * OUT_DIM))[lane];
    float4 o;
    o.x = a.x * nd + ALPHA * z.x;
    o.y = a.y * nd + ALPHA * z.y;
    o.z = a.z * nd + ALPHA * z.z;
    o.w = a.w * nd + ALPHA * z.w;
    ((float4*)(fout + (size_t)node * OUT_DIM))[lane] = o;
}

// ---------------- attention score dots: warp per node ----------------
__global__ void dots_kernel(const float* __restrict__ feat,
                            const float* __restrict__ wsrc,
                            const float* __restrict__ wdst) {
    int node = (blockIdx.x * blockDim.x + threadIdx.x) >> 5;
    if (node >= N_NODES) return;
    int lane = threadIdx.x & 31;
    float2 f = ((const float2*)(feat + (size_t)node * OUT_DIM))[lane];
    float2 a = ((const float2*)wsrc)[lane];
    float2 b = ((const float2*)wdst)[lane];
    float s = f.x * a.x + f.y * a.y;
    float d = f.x * b.x + f.y * b.y;
    #pragma unroll
    for (int off = 16; off; off >>= 1) {
        s += __shfl_xor_sync(0xffffffffu, s, off);
        d += __shfl_xor_sync(0xffffffffu, d, off);
    }
    if (lane == 0) {
        g_es[node] = s;
        g_ed[node] = d;
    }
}

// ---------------- attention softmax over in-edges: warp per node ----------
__global__ void attn_kernel(float* __restrict__ attn_out) {
    int node = (blockIdx.x * blockDim.x + threadIdx.x) >> 5;
    if (node >= N_NODES) return;
    int lane = threadIdx.x & 31;
    int beg = g_row_ptr[node], end = g_row_ptr[node + 1];
    int deg = end - beg;
    if (deg == 0) return;
    float edv = g_ed[node];

    if (deg <= 32) {
        int p = beg + lane;
        bool act = p < end;
        float e = act ? tanhf(g_es[g_csr_src[p]] + edv) : -INFINITY;
        float m = e;
        #pragma unroll
        for (int off = 16; off; off >>= 1) m = fmaxf(m, __shfl_xor_sync(0xffffffffu, m, off));
        float ex = act ? expf(e - m) : 0.f;
        float s = ex;
        #pragma unroll
        for (int off = 16; off; off >>= 1) s += __shfl_xor_sync(0xffffffffu, s, off);
        if (act) attn_out[g_csr_eid[p]] = ex / s;
        return;
    }

    float m = -INFINITY;
    for (int p = beg + lane; p < end; p += 32) {
        float e = tanhf(g_es[g_csr_src[p]] + edv);
        g_etmp[p] = e;
        m = fmaxf(m, e);
    }
    #pragma unroll
    for (int off = 16; off; off >>= 1) m = fmaxf(m, __shfl_xor_sync(0xffffffffu, m, off));
    float s = 0.f;
    for (int p = beg + lane; p < end; p += 32) {
        float ex = expf(g_etmp[p] - m);
        g_etmp[p] = ex;
        s += ex;
    }
    #pragma unroll
    for (int off = 16; off; off >>= 1) s += __shfl_xor_sync(0xffffffffu, s, off);
    float inv = 1.f / s;
    for (int p = beg + lane; p < end; p += 32) {
        attn_out[g_csr_eid[p]] = g_etmp[p] * inv;
    }
}

// ---------------- log_softmax over 64 features: warp per node -------------
__global__ void lsm_kernel(const float* __restrict__ feat, float* __restrict__ out) {
    int node = (blockIdx.x * blockDim.x + threadIdx.x) >> 5;
    if (node >= N_NODES) return;
    int lane = threadIdx.x & 31;
    float2 f = ((const float2*)(feat + (size_t)node * OUT_DIM))[lane];
    float m = fmaxf(f.x, f.y);
    #pragma unroll
    for (int off = 16; off; off >>= 1) m = fmaxf(m, __shfl_xor_sync(0xffffffffu, m, off));
    float s = expf(f.x - m) + expf(f.y - m);
    #pragma unroll
    for (int off = 16; off; off >>= 1) s += __shfl_xor_sync(0xffffffffu, s, off);
    float lse = m + logf(s);
    float2 o;
    o.x = f.x - lse;
    o.y = f.y - lse;
    ((float2*)(out + (size_t)node * OUT_DIM))[lane] = o;
}

// ---------------- launch ----------------
extern "C" void kernel_launch(void* const* d_in, const int* in_sizes, int n_in,
                              void* d_out, int out_size) {
    const float* h   = (const float*)d_in[0];
    const int*   src = (const int*)d_in[1];
    const int*   dst = (const int*)d_in[2];
    const float* W1  = (const float*)d_in[3];
    const float* b1  = (const float*)d_in[4];
    const float* W2  = (const float*)d_in[5];
    const float* b2  = (const float*)d_in[6];
    const float* wsr = (const float*)d_in[7];
    const float* wds = (const float*)d_in[8];
    float* out = (float*)d_out;

    __half *p_h16, *p_w1h, *p_w1l, *p_w2h, *p_w2l, *p_hid16;
    float *p_x0, *p_fA, *p_fB;
    cudaGetSymbolAddress((void**)&p_h16, g_h16);
    cudaGetSymbolAddress((void**)&p_w1h, g_w1h);
    cudaGetSymbolAddress((void**)&p_w1l, g_w1l);
    cudaGetSymbolAddress((void**)&p_w2h, g_w2h);
    cudaGetSymbolAddress((void**)&p_w2l, g_w2l);
    cudaGetSymbolAddress((void**)&p_hid16, g_hid16);
    cudaGetSymbolAddress((void**)&p_x0, g_x0);
    cudaGetSymbolAddress((void**)&p_fA, g_fA);
    cudaGetSymbolAddress((void**)&p_fB, g_fB);

    const int TPB = 256;
    int nodeBlocks = (N_NODES + TPB - 1) / TPB;
    int edgeBlocks = (N_EDGES + TPB - 1) / TPB;
    int warpNodeBlocks = (N_NODES * 32 + TPB - 1) / TPB;
    int hwNodeBlocks = (N_NODES * 16 + TPB - 1) / TPB;

    // 1-3: zero + conversions (gemm1 kept in capture slot 4)
    zero3_kernel<<<nodeBlocks, TPB>>>();
    {
        int n4 = N_NODES * IN_DIM / 4;
        f32_to_f16_kernel<<<(n4 + TPB - 1) / TPB, TPB>>>(h, p_h16, n4);
        int w4 = IN_DIM * HID_DIM / 4;
        f32_split_f16_kernel<<<(w4 + TPB - 1) / TPB, TPB>>>(W1, p_w1h, p_w1l, w4);
    }

    // 4: GEMM1  hidden16 = fp16(relu(h @ W1 + b1))
    {
        dim3 grid1(HID_DIM / 128, (N_NODES + GBM - 1) / GBM);
        gemm_f16_kernel<128, true, true><<<grid1, 256>>>(
            p_h16, p_w1h, p_w1l, b1, nullptr, p_hid16, N_NODES, HID_DIM, IN_DIM);
    }

    {
        int w4 = HID_DIM * OUT_DIM / 4;
        f32_split_f16_kernel<<<(w4 + TPB - 1) / TPB, TPB>>>(W2, p_w2h, p_w2l, w4);
    }
    count_deg_kernel<<<edgeBlocks, TPB>>>(src, dst);
    norm_kernel<<<nodeBlocks, TPB>>>();
    scan1_kernel<<<SCAN_NBLK, SCAN_BLK>>>();
    scan2_kernel<<<1, 1>>>();
    scan3_kernel<<<SCAN_NBLK, SCAN_BLK>>>();
    build_csr_kernel<<<edgeBlocks, TPB>>>(src, dst);

    // GEMM2  x0 = hidden @ W2 + b2
    {
        dim3 grid2(OUT_DIM / 64, (N_NODES + GBM - 1) / GBM);
        gemm_f16_kernel<64, false, false><<<grid2, 256>>>(
            p_hid16, p_w2h, p_w2l, b2, p_x0, nullptr, N_NODES, OUT_DIM, HID_DIM);
    }

    // K_HOPS=4 propagation, ping-pong buffers; final result in g_fB
    prop_kernel<<<hwNodeBlocks, TPB>>>(p_x0, p_fA);
    prop_kernel<<<hwNodeBlocks, TPB>>>(p_fA, p_fB);
    prop_kernel<<<hwNodeBlocks, TPB>>>(p_fB, p_fA);
    prop_kernel<<<hwNodeBlocks, TPB>>>(p_fA, p_fB);

    // attention
    dots_kernel<<<warpNodeBlocks, TPB>>>(p_fB, wsr, wds);
    attn_kernel<<<warpNodeBlocks, TPB>>>(out + (size_t)N_NODES * OUT_DIM);

    // log_softmax output
    lsm_kernel<<<warpNodeBlocks, TPB>>>(p_fB, out);
}

// round 7
// speedup vs baseline: 2.0875x; 1.1481x over previous
#include <cuda_runtime.h>
#include <cuda_bf16.h>
#include <cuda_fp16.h>
#include <math.h>
#include <stdint.h>

#define N_NODES 50000
#define N_EDGES 1600000
#define IN_DIM 512
#define HID_DIM 256
#define OUT_DIM 64
#define K_HOPS 4
#define ALPHA 0.1f

#define SCAN_BLK 1024
#define SCAN_NBLK ((N_NODES + SCAN_BLK - 1) / SCAN_BLK)   // 49

// ---------------- device scratch (no allocs allowed) ----------------
__device__ __half  g_h16[(size_t)N_NODES * IN_DIM];
__device__ __half  g_w1[IN_DIM * HID_DIM];
__device__ __half  g_w2[HID_DIM * OUT_DIM];
__device__ __half  g_hid16[(size_t)N_NODES * HID_DIM];
__device__ float g_x0[(size_t)N_NODES * OUT_DIM];
__device__ float g_fA[(size_t)N_NODES * OUT_DIM];
__device__ float g_fB[(size_t)N_NODES * OUT_DIM];
__device__ int   g_deg_out[N_NODES];
__device__ int   g_deg_in[N_NODES];
__device__ int   g_fill[N_NODES];
__device__ int   g_row_ptr[N_NODES + 1];
__device__ float g_nsrc[N_NODES];
__device__ float g_ndst[N_NODES];
__device__ int   g_csr_src[N_EDGES];
__device__ int   g_csr_eid[N_EDGES];
__device__ float g_es[N_NODES];
__device__ float g_ed[N_NODES];
__device__ float g_etmp[N_EDGES];
__device__ int   g_bsum[SCAN_NBLK];
__device__ int   g_boff[SCAN_NBLK];

// ---------------- conversion kernel ----------------
__global__ void f32_to_f16_kernel(const float* __restrict__ in,
                                  __half* __restrict__ out, int n4) {
    int i = blockIdx.x * blockDim.x + threadIdx.x;
    if (i < n4) {
        float4 v = ((const float4*)in)[i];
        __half2 a = __floats2half2_rn(v.x, v.y);
        __half2 b = __floats2half2_rn(v.z, v.w);
        uint2 u;
        u.x = *(uint32_t*)&a;
        u.y = *(uint32_t*)&b;
        ((uint2*)out)[i] = u;
    }
}

// ---------------- small kernels ----------------
__global__ void zero3_kernel() {
    int i = blockIdx.x * blockDim.x + threadIdx.x;
    if (i < N_NODES) {
        g_deg_out[i] = 0;
        g_deg_in[i]  = 0;
        g_fill[i]    = 0;
    }
}

__global__ void count_deg_kernel(const int* __restrict__ src, const int* __restrict__ dst) {
    int e = blockIdx.x * blockDim.x + threadIdx.x;
    if (e < N_EDGES) {
        atomicAdd(&g_deg_out[src[e]], 1);
        atomicAdd(&g_deg_in[dst[e]], 1);
    }
}

__global__ void norm_kernel() {
    int i = blockIdx.x * blockDim.x + threadIdx.x;
    if (i < N_NODES) {
        int doo = g_deg_out[i]; if (doo < 1) doo = 1;
        int din = g_deg_in[i];  if (din < 1) din = 1;
        g_nsrc[i] = rsqrtf((float)doo);
        g_ndst[i] = rsqrtf((float)din);
    }
}

// ---- 3-phase grid-wide exclusive scan of g_deg_in -> g_row_ptr ----
__global__ void scan1_kernel() {
    __shared__ int warpsum[32];
    int tid = threadIdx.x, lane = tid & 31, wid = tid >> 5;
    int i = blockIdx.x * SCAN_BLK + tid;
    int v = (i < N_NODES) ? g_deg_in[i] : 0;
    int x = v;
    #pragma unroll
    for (int off = 1; off < 32; off <<= 1) {
        int t = __shfl_up_sync(0xffffffffu, x, off);
        if (lane >= off) x += t;
    }
    if (lane == 31) warpsum[wid] = x;
    __syncthreads();
    if (wid == 0) {
        int w = warpsum[lane];
        #pragma unroll
        for (int off = 1; off < 32; off <<= 1) {
            int t = __shfl_up_sync(0xffffffffu, w, off);
            if (lane >= off) w += t;
        }
        warpsum[lane] = w;
    }
    __syncthreads();
    int offset = (wid > 0) ? warpsum[wid - 1] : 0;
    if (i < N_NODES) g_row_ptr[i] = x + offset - v;
    if (tid == SCAN_BLK - 1) g_bsum[blockIdx.x] = x + offset;
}

__global__ void scan2_kernel() {
    int run = 0;
    for (int i = 0; i < SCAN_NBLK; i++) {
        g_boff[i] = run;
        run += g_bsum[i];
    }
    g_row_ptr[N_NODES] = run;
}

__global__ void scan3_kernel() {
    int i = blockIdx.x * SCAN_BLK + threadIdx.x;
    if (i < N_NODES && blockIdx.x > 0) g_row_ptr[i] += g_boff[blockIdx.x];
}

__global__ void build_csr_kernel(const int* __restrict__ src, const int* __restrict__ dst) {
    int e = blockIdx.x * blockDim.x + threadIdx.x;
    if (e < N_EDGES) {
        int d = dst[e];
        int pos = g_row_ptr[d] + atomicAdd(&g_fill[d], 1);
        g_csr_src[pos] = src[e];
        g_csr_eid[pos] = e;
    }
}

// ---------------- fp16 tensor-core GEMM, 4-stage cp.async, static smem ---
__device__ __forceinline__ uint32_t smem_u32(const void* p) {
    return (uint32_t)__cvta_generic_to_shared(p);
}
__device__ __forceinline__ void cp_async16(uint32_t s, const void* g) {
    asm volatile("cp.async.cg.shared.global [%0], [%1], 16;\n"
        :: "r"(s), "l"(__cvta_generic_to_global(g)));
}
__device__ __forceinline__ void cp_commit() {
    asm volatile("cp.async.commit_group;\n");
}
template <int NW>
__device__ __forceinline__ void cp_wait() {
    asm volatile("cp.async.wait_group %0;\n" :: "n"(NW));
}
__device__ __forceinline__ void ldsm_x4(uint32_t* r, uint32_t addr) {
    asm volatile("ldmatrix.sync.aligned.m8n8.x4.shared.b16 {%0,%1,%2,%3}, [%4];\n"
        : "=r"(r[0]), "=r"(r[1]), "=r"(r[2]), "=r"(r[3]) : "r"(addr));
}
__device__ __forceinline__ void ldsm_x4_trans(uint32_t* r, uint32_t addr) {
    asm volatile("ldmatrix.sync.aligned.m8n8.x4.trans.shared.b16 {%0,%1,%2,%3}, [%4];\n"
        : "=r"(r[0]), "=r"(r[1]), "=r"(r[2]), "=r"(r[3]) : "r"(addr));
}
__device__ __forceinline__ void mma16816h(float* c, const uint32_t* a, const uint32_t* b) {
    asm volatile(
        "mma.sync.aligned.m16n8k16.row.col.f32.f16.f16.f32 "
        "{%0,%1,%2,%3}, {%4,%5,%6,%7}, {%8,%9}, {%0,%1,%2,%3};\n"
        : "+f"(c[0]), "+f"(c[1]), "+f"(c[2]), "+f"(c[3])
        : "r"(a[0]), "r"(a[1]), "r"(a[2]), "r"(a[3]), "r"(b[0]), "r"(b[1]));
}

#define GBM 128
#define GBK 16
#define GSTAGES 4

// C = A(fp16) @ B(fp16) + bias; static smem 41KB (BN=128) / 28.5KB (BN=64)
template <int BN, bool RELU, bool OUT16>
__global__ __launch_bounds__(256)
void gemm_f16_kernel(const __half* __restrict__ A,
                     const __half* __restrict__ B,
                     const float* __restrict__ bias,
                     float* __restrict__ Cf,
                     __half* __restrict__ C16,
                     int M, int N, int K) {
    constexpr int WN  = BN / 2;
    constexpr int NJ  = WN / 8;
    constexpr int NJP = NJ / 2;
    __shared__ __align__(16) __half As[GSTAGES][GBM][GBK + 8];
    __shared__ __align__(16) __half Bs[GSTAGES][GBK][BN + 8];

    int tid = threadIdx.x;
    int lane = tid & 31, wid = tid >> 5;
    int wm = wid & 3, wn = wid >> 2;
    int rowBase = blockIdx.y * GBM;
    int colBase = blockIdx.x * BN;

    float acc[2][NJ][4];
    #pragma unroll
    for (int i = 0; i < 2; i++)
        #pragma unroll
        for (int j = 0; j < NJ; j++)
            #pragma unroll
            for (int q = 0; q < 4; q++) acc[i][j][q] = 0.f;

    auto load_stage = [&](int s, int k0) {
        // A: 128x16 halves = 256 16B chunks (1/thread)
        {
            int r = tid >> 1;
            int c8 = (tid & 1) << 3;
            int row = rowBase + r;
            if (row > M - 1) row = M - 1;
            cp_async16(smem_u32(&As[s][r][c8]), A + (size_t)row * K + k0 + c8);
        }
        // B: 16xBN halves = 2*BN chunks
        #pragma unroll
        for (int q = tid; q < 2 * BN; q += 256) {
            int r = q / (BN / 8);
            int c8 = (q % (BN / 8)) << 3;
            cp_async16(smem_u32(&Bs[s][r][c8]), B + (size_t)(k0 + r) * N + colBase + c8);
        }
        cp_commit();
    };

    int T = K / GBK;
    load_stage(0, 0);
    load_stage(1, GBK);
    load_stage(2, 2 * GBK);

    for (int t = 0; t < T; t++) {
        cp_wait<GSTAGES - 2>();      // oldest outstanding (stage t) complete
        __syncthreads();             // single barrier per iteration
        int pf = t + GSTAGES - 1;
        if (pf < T) load_stage(pf % GSTAGES, pf * GBK);
        int cur = t % GSTAGES;

        uint32_t a[2][4];
        #pragma unroll
        for (int mi = 0; mi < 2; mi++) {
            int r = wm * 32 + mi * 16 + (lane & 15);
            int c = (lane >> 4) << 3;
            ldsm_x4(a[mi], smem_u32(&As[cur][r][c]));
        }
        uint32_t b[NJ][2];
        #pragma unroll
        for (int p = 0; p < NJP; p++) {
            int r = (lane & 7) + (lane & 8);
            int c = wn * WN + p * 16 + ((lane >> 4) << 3);
            uint32_t tt[4];
            ldsm_x4_trans(tt, smem_u32(&Bs[cur][r][c]));
            b[2 * p][0] = tt[0]; b[2 * p][1] = tt[1];
            b[2 * p + 1][0] = tt[2]; b[2 * p + 1][1] = tt[3];
        }
        #pragma unroll
        for (int mi = 0; mi < 2; mi++)
            #pragma unroll
            for (int nj = 0; nj < NJ; nj++)
                mma16816h(acc[mi][nj], a[mi], b[nj]);
        // no trailing barrier: next iteration's leading barrier protects the
        // stage ring (loads in iter t+1 target stage (t+4)%4 = t%4, but only
        // after every warp has passed iter t+1's __syncthreads, i.e. finished
        // reading stage t%4).
    }

    // epilogue
    int g = lane >> 2, tig = lane & 3;
    #pragma unroll
    for (int mi = 0; mi < 2; mi++) {
        int row0 = rowBase + wm * 32 + mi * 16 + g;
        int row1 = row0 + 8;
        #pragma unroll
        for (int nj = 0; nj < NJ; nj++) {
            int col = colBase + wn * WN + nj * 8 + 2 * tig;
            float bv0 = bias[col], bv1 = bias[col + 1];
            float v0 = acc[mi][nj][0] + bv0;
            float v1 = acc[mi][nj][1] + bv1;
            float v2 = acc[mi][nj][2] + bv0;
            float v3 = acc[mi][nj][3] + bv1;
            if (RELU) {
                v0 = fmaxf(v0, 0.f); v1 = fmaxf(v1, 0.f);
                v2 = fmaxf(v2, 0.f); v3 = fmaxf(v3, 0.f);
            }
            if (OUT16) {
                if (row0 < M) *(__half2*)&C16[(size_t)row0 * N + col] = __floats2half2_rn(v0, v1);
                if (row1 < M) *(__half2*)&C16[(size_t)row1 * N + col] = __floats2half2_rn(v2, v3);
            } else {
                if (row0 < M) {
                    Cf[(size_t)row0 * N + col]     = v0;
                    Cf[(size_t)row0 * N + col + 1] = v1;
                }
                if (row1 < M) {
                    Cf[(size_t)row1 * N + col]     = v2;
                    Cf[(size_t)row1 * N + col + 1] = v3;
                }
            }
        }
    }
}

// ---------------- propagation hop: half-warp per node, float4/lane --------
__global__ void prop_kernel(const float* __restrict__ fin, float* __restrict__ fout) {
    int node = (blockIdx.x * blockDim.x + threadIdx.x) >> 4;
    if (node >= N_NODES) return;
    int lane = threadIdx.x & 15;
    int beg = g_row_ptr[node], end = g_row_ptr[node + 1];
    float4 a = make_float4(0.f, 0.f, 0.f, 0.f);
    int p = beg;
    for (; p + 2 <= end; p += 2) {
        int s0 = g_csr_src[p];
        int s1 = g_csr_src[p + 1];
        float ns0 = g_nsrc[s0];
        float ns1 = g_nsrc[s1];
        float4 v0 = ((const float4*)(fin + (size_t)s0 * OUT_DIM))[lane];
        float4 v1 = ((const float4*)(fin + (size_t)s1 * OUT_DIM))[lane];
        a.x += v0.x * ns0 + v1.x * ns1;
        a.y += v0.y * ns0 + v1.y * ns1;
        a.z += v0.z * ns0 + v1.z * ns1;
        a.w += v0.w * ns0 + v1.w * ns1;
    }
    if (p < end) {
        int s = g_csr_src[p];
        float ns = g_nsrc[s];
        float4 v = ((const float4*)(fin + (size_t)s * OUT_DIM))[lane];
        a.x += v.x * ns; a.y += v.y * ns; a.z += v.z * ns; a.w += v.w * ns;
    }
    float nd = (1.f - ALPHA) * g_ndst[node];
    float4 z = ((const float4*)(g_x0 + (size_t)node * OUT_DIM))[lane];
    float4 o;
    o.x = a.x * nd + ALPHA * z.x;
    o.y = a.y * nd + ALPHA * z.y;
    o.z = a.z * nd + ALPHA * z.z;
    o.w = a.w * nd + ALPHA * z.w;
    ((float4*)(fout + (size_t)node * OUT_DIM))[lane] = o;
}

// ---------------- attention score dots: warp per node ----------------
__global__ void dots_kernel(const float* __restrict__ feat,
                            const float* __restrict__ wsrc,
                            const float* __restrict__ wdst) {
    int node = (blockIdx.x * blockDim.x + threadIdx.x) >> 5;
    if (node >= N_NODES) return;
    int lane = threadIdx.x & 31;
    float2 f = ((const float2*)(feat + (size_t)node * OUT_DIM))[lane];
    float2 a = ((const float2*)wsrc)[lane];
    float2 b = ((const float2*)wdst)[lane];
    float s = f.x * a.x + f.y * a.y;
    float d = f.x * b.x + f.y * b.y;
    #pragma unroll
    for (int off = 16; off; off >>= 1) {
        s += __shfl_xor_sync(0xffffffffu, s, off);
        d += __shfl_xor_sync(0xffffffffu, d, off);
    }
    if (lane == 0) {
        g_es[node] = s;
        g_ed[node] = d;
    }
}

// ---------------- attention softmax over in-edges: warp per node ----------
__global__ void attn_kernel(float* __restrict__ attn_out) {
    int node = (blockIdx.x * blockDim.x + threadIdx.x) >> 5;
    if (node >= N_NODES) return;
    int lane = threadIdx.x & 31;
    int beg = g_row_ptr[node], end = g_row_ptr[node + 1];
    int deg = end - beg;
    if (deg == 0) return;
    float edv = g_ed[node];

    if (deg <= 32) {
        int p = beg + lane;
        bool act = p < end;
        float e = act ? tanhf(g_es[g_csr_src[p]] + edv) : -INFINITY;
        float m = e;
        #pragma unroll
        for (int off = 16; off; off >>= 1) m = fmaxf(m, __shfl_xor_sync(0xffffffffu, m, off));
        float ex = act ? expf(e - m) : 0.f;
        float s = ex;
        #pragma unroll
        for (int off = 16; off; off >>= 1) s += __shfl_xor_sync(0xffffffffu, s, off);
        if (act) attn_out[g_csr_eid[p]] = ex / s;
        return;
    }

    float m = -INFINITY;
    for (int p = beg + lane; p < end; p += 32) {
        float e = tanhf(g_es[g_csr_src[p]] + edv);
        g_etmp[p] = e;
        m = fmaxf(m, e);
    }
    #pragma unroll
    for (int off = 16; off; off >>= 1) m = fmaxf(m, __shfl_xor_sync(0xffffffffu, m, off));
    float s = 0.f;
    for (int p = beg + lane; p < end; p += 32) {
        float ex = expf(g_etmp[p] - m);
        g_etmp[p] = ex;
        s += ex;
    }
    #pragma unroll
    for (int off = 16; off; off >>= 1) s += __shfl_xor_sync(0xffffffffu, s, off);
    float inv = 1.f / s;
    for (int p = beg + lane; p < end; p += 32) {
        attn_out[g_csr_eid[p]] = g_etmp[p] * inv;
    }
}

// ---------------- log_softmax over 64 features: warp per node -------------
__global__ void lsm_kernel(const float* __restrict__ feat, float* __restrict__ out) {
    int node = (blockIdx.x * blockDim.x + threadIdx.x) >> 5;
    if (node >= N_NODES) return;
    int lane = threadIdx.x & 31;
    float2 f = ((const float2*)(feat + (size_t)node * OUT_DIM))[lane];
    float m = fmaxf(f.x, f.y);
    #pragma unroll
    for (int off = 16; off; off >>= 1) m = fmaxf(m, __shfl_xor_sync(0xffffffffu, m, off));
    float s = expf(f.x - m) + expf(f.y - m);
    #pragma unroll
    for (int off = 16; off; off >>= 1) s += __shfl_xor_sync(0xffffffffu, s, off);
    float lse = m + logf(s);
    float2 o;
    o.x = f.x - lse;
    o.y = f.y - lse;
    ((float2*)(out + (size_t)node * OUT_DIM))[lane] = o;
}

// ---------------- launch ----------------
extern "C" void kernel_launch(void* const* d_in, const int* in_sizes, int n_in,
                              void* d_out, int out_size) {
    const float* h   = (const float*)d_in[0];
    const int*   src = (const int*)d_in[1];
    const int*   dst = (const int*)d_in[2];
    const float* W1  = (const float*)d_in[3];
    const float* b1  = (const float*)d_in[4];
    const float* W2  = (const float*)d_in[5];
    const float* b2  = (const float*)d_in[6];
    const float* wsr = (const float*)d_in[7];
    const float* wds = (const float*)d_in[8];
    float* out = (float*)d_out;

    __half *p_h16, *p_w1, *p_w2, *p_hid16;
    float *p_x0, *p_fA, *p_fB;
    cudaGetSymbolAddress((void**)&p_h16, g_h16);
    cudaGetSymbolAddress((void**)&p_w1, g_w1);
    cudaGetSymbolAddress((void**)&p_w2, g_w2);
    cudaGetSymbolAddress((void**)&p_hid16, g_hid16);
    cudaGetSymbolAddress((void**)&p_x0, g_x0);
    cudaGetSymbolAddress((void**)&p_fA, g_fA);
    cudaGetSymbolAddress((void**)&p_fB, g_fB);

    const int TPB = 256;
    int nodeBlocks = (N_NODES + TPB - 1) / TPB;
    int edgeBlocks = (N_EDGES + TPB - 1) / TPB;
    int warpNodeBlocks = (N_NODES * 32 + TPB - 1) / TPB;
    int hwNodeBlocks = (N_NODES * 16 + TPB - 1) / TPB;

    // 1-3: zero + conversions (gemm1 kept in ncu capture slot 4)
    zero3_kernel<<<nodeBlocks, TPB>>>();
    {
        int n4 = N_NODES * IN_DIM / 4;
        f32_to_f16_kernel<<<(n4 + TPB - 1) / TPB, TPB>>>(h, p_h16, n4);
        int w4 = IN_DIM * HID_DIM / 4;
        f32_to_f16_kernel<<<(w4 + TPB - 1) / TPB, TPB>>>(W1, p_w1, w4);
    }

    // 4: GEMM1  hidden16 = fp16(relu(h @ W1 + b1))
    {
        dim3 grid1(HID_DIM / 128, (N_NODES + GBM - 1) / GBM);
        gemm_f16_kernel<128, true, true><<<grid1, 256>>>(
            p_h16, p_w1, b1, nullptr, p_hid16, N_NODES, HID_DIM, IN_DIM);
    }

    {
        int w4 = HID_DIM * OUT_DIM / 4;
        f32_to_f16_kernel<<<(w4 + TPB - 1) / TPB, TPB>>>(W2, p_w2, w4);
    }
    count_deg_kernel<<<edgeBlocks, TPB>>>(src, dst);
    norm_kernel<<<nodeBlocks, TPB>>>();
    scan1_kernel<<<SCAN_NBLK, SCAN_BLK>>>();
    scan2_kernel<<<1, 1>>>();
    scan3_kernel<<<SCAN_NBLK, SCAN_BLK>>>();
    build_csr_kernel<<<edgeBlocks, TPB>>>(src, dst);

    // GEMM2  x0 = hidden @ W2 + b2
    {
        dim3 grid2(OUT_DIM / 64, (N_NODES + GBM - 1) / GBM);
        gemm_f16_kernel<64, false, false><<<grid2, 256>>>(
            p_hid16, p_w2, b2, p_x0, nullptr, N_NODES, OUT_DIM, HID_DIM);
    }

    // K_HOPS=4 propagation, ping-pong buffers; final result in g_fB
    prop_kernel<<<hwNodeBlocks, TPB>>>(p_x0, p_fA);
    prop_kernel<<<hwNodeBlocks, TPB>>>(p_fA, p_fB);
    prop_kernel<<<hwNodeBlocks, TPB>>>(p_fB, p_fA);
    prop_kernel<<<hwNodeBlocks, TPB>>>(p_fA, p_fB);

    // attention
    dots_kernel<<<warpNodeBlocks, TPB>>>(p_fB, wsr, wds);
    attn_kernel<<<warpNodeBlocks, TPB>>>(out + (size_t)N_NODES * OUT_DIM);

    // log_softmax output
    lsm_kernel<<<warpNodeBlocks, TPB>>>(p_fB, out);
}

// round 8
// speedup vs baseline: 2.1405x; 1.0254x over previous
#include <cuda_runtime.h>
#include <cuda_bf16.h>
#include <cuda_fp16.h>
#include <math.h>
#include <stdint.h>

#define N_NODES 50000
#define N_EDGES 1600000
#define IN_DIM 512
#define HID_DIM 256
#define OUT_DIM 64
#define K_HOPS 4
#define ALPHA 0.1f

#define SCAN_BLK 1024
#define SCAN_NBLK ((N_NODES + SCAN_BLK - 1) / SCAN_BLK)   // 49

// ---------------- device scratch (no allocs allowed) ----------------
__device__ __half  g_h16[(size_t)N_NODES * IN_DIM];
__device__ __half  g_w1[IN_DIM * HID_DIM];
__device__ __half  g_w2[HID_DIM * OUT_DIM];
__device__ __half  g_hid16[(size_t)N_NODES * HID_DIM];
__device__ __half  g_x016[(size_t)N_NODES * OUT_DIM];   // feat0 fp16
__device__ __half  g_fA16[(size_t)N_NODES * OUT_DIM];
__device__ __half  g_fB16[(size_t)N_NODES * OUT_DIM];
__device__ int   g_deg_out[N_NODES];
__device__ int   g_deg_in[N_NODES];
__device__ int   g_fill[N_NODES];
__device__ int   g_row_ptr[N_NODES + 1];
__device__ float g_nsrc[N_NODES];
__device__ float g_ndst[N_NODES];
__device__ int   g_csr_src[N_EDGES];
__device__ int   g_csr_eid[N_EDGES];
__device__ float g_es[N_NODES];
__device__ float g_ed[N_NODES];
__device__ float g_etmp[N_EDGES];
__device__ int   g_bsum[SCAN_NBLK];
__device__ int   g_boff[SCAN_NBLK];

// ---------------- conversion kernel ----------------
__global__ void f32_to_f16_kernel(const float* __restrict__ in,
                                  __half* __restrict__ out, int n4) {
    int i = blockIdx.x * blockDim.x + threadIdx.x;
    if (i < n4) {
        float4 v = ((const float4*)in)[i];
        __half2 a = __floats2half2_rn(v.x, v.y);
        __half2 b = __floats2half2_rn(v.z, v.w);
        uint2 u;
        u.x = *(uint32_t*)&a;
        u.y = *(uint32_t*)&b;
        ((uint2*)out)[i] = u;
    }
}

// ---------------- small kernels ----------------
__global__ void zero3_kernel() {
    int i = blockIdx.x * blockDim.x + threadIdx.x;
    if (i < N_NODES) {
        g_deg_out[i] = 0;
        g_deg_in[i]  = 0;
        g_fill[i]    = 0;
    }
}

__global__ void count_deg_kernel(const int* __restrict__ src, const int* __restrict__ dst) {
    int e = blockIdx.x * blockDim.x + threadIdx.x;
    if (e < N_EDGES) {
        atomicAdd(&g_deg_out[src[e]], 1);
        atomicAdd(&g_deg_in[dst[e]], 1);
    }
}

__global__ void norm_kernel() {
    int i = blockIdx.x * blockDim.x + threadIdx.x;
    if (i < N_NODES) {
        int doo = g_deg_out[i]; if (doo < 1) doo = 1;
        int din = g_deg_in[i];  if (din < 1) din = 1;
        g_nsrc[i] = rsqrtf((float)doo);
        g_ndst[i] = rsqrtf((float)din);
    }
}

// ---- 3-phase grid-wide exclusive scan of g_deg_in -> g_row_ptr ----
__global__ void scan1_kernel() {
    __shared__ int warpsum[32];
    int tid = threadIdx.x, lane = tid & 31, wid = tid >> 5;
    int i = blockIdx.x * SCAN_BLK + tid;
    int v = (i < N_NODES) ? g_deg_in[i] : 0;
    int x = v;
    #pragma unroll
    for (int off = 1; off < 32; off <<= 1) {
        int t = __shfl_up_sync(0xffffffffu, x, off);
        if (lane >= off) x += t;
    }
    if (lane == 31) warpsum[wid] = x;
    __syncthreads();
    if (wid == 0) {
        int w = warpsum[lane];
        #pragma unroll
        for (int off = 1; off < 32; off <<= 1) {
            int t = __shfl_up_sync(0xffffffffu, w, off);
            if (lane >= off) w += t;
        }
        warpsum[lane] = w;
    }
    __syncthreads();
    int offset = (wid > 0) ? warpsum[wid - 1] : 0;
    if (i < N_NODES) g_row_ptr[i] = x + offset - v;
    if (tid == SCAN_BLK - 1) g_bsum[blockIdx.x] = x + offset;
}

__global__ void scan2_kernel() {
    int run = 0;
    for (int i = 0; i < SCAN_NBLK; i++) {
        g_boff[i] = run;
        run += g_bsum[i];
    }
    g_row_ptr[N_NODES] = run;
}

__global__ void scan3_kernel() {
    int i = blockIdx.x * SCAN_BLK + threadIdx.x;
    if (i < N_NODES && blockIdx.x > 0) g_row_ptr[i] += g_boff[blockIdx.x];
}

__global__ void build_csr_kernel(const int* __restrict__ src, const int* __restrict__ dst) {
    int e = blockIdx.x * blockDim.x + threadIdx.x;
    if (e < N_EDGES) {
        int d = dst[e];
        int pos = g_row_ptr[d] + atomicAdd(&g_fill[d], 1);
        g_csr_src[pos] = src[e];
        g_csr_eid[pos] = e;
    }
}

// ---------------- fp16 tensor-core GEMM, 4-stage cp.async, static smem ---
__device__ __forceinline__ uint32_t smem_u32(const void* p) {
    return (uint32_t)__cvta_generic_to_shared(p);
}
__device__ __forceinline__ void cp_async16(uint32_t s, const void* g) {
    asm volatile("cp.async.cg.shared.global [%0], [%1], 16;\n"
        :: "r"(s), "l"(__cvta_generic_to_global(g)));
}
__device__ __forceinline__ void cp_commit() {
    asm volatile("cp.async.commit_group;\n");
}
template <int NW>
__device__ __forceinline__ void cp_wait() {
    asm volatile("cp.async.wait_group %0;\n" :: "n"(NW));
}
__device__ __forceinline__ void ldsm_x4(uint32_t* r, uint32_t addr) {
    asm volatile("ldmatrix.sync.aligned.m8n8.x4.shared.b16 {%0,%1,%2,%3}, [%4];\n"
        : "=r"(r[0]), "=r"(r[1]), "=r"(r[2]), "=r"(r[3]) : "r"(addr));
}
__device__ __forceinline__ void ldsm_x4_trans(uint32_t* r, uint32_t addr) {
    asm volatile("ldmatrix.sync.aligned.m8n8.x4.trans.shared.b16 {%0,%1,%2,%3}, [%4];\n"
        : "=r"(r[0]), "=r"(r[1]), "=r"(r[2]), "=r"(r[3]) : "r"(addr));
}
__device__ __forceinline__ void mma16816h(float* c, const uint32_t* a, const uint32_t* b) {
    asm volatile(
        "mma.sync.aligned.m16n8k16.row.col.f32.f16.f16.f32 "
        "{%0,%1,%2,%3}, {%4,%5,%6,%7}, {%8,%9}, {%0,%1,%2,%3};\n"
        : "+f"(c[0]), "+f"(c[1]), "+f"(c[2]), "+f"(c[3])
        : "r"(a[0]), "r"(a[1]), "r"(a[2]), "r"(a[3]), "r"(b[0]), "r"(b[1]));
}

#define GBM 128
#define GBK 16
#define GSTAGES 4

// C = A(fp16) @ B(fp16) + bias; static smem 41KB (BN=128) / 28.5KB (BN=64)
template <int BN, bool RELU, bool OUT16>
__global__ __launch_bounds__(256)
void gemm_f16_kernel(const __half* __restrict__ A,
                     const __half* __restrict__ B,
                     const float* __restrict__ bias,
                     float* __restrict__ Cf,
                     __half* __restrict__ C16,
                     int M, int N, int K) {
    constexpr int WN  = BN / 2;
    constexpr int NJ  = WN / 8;
    constexpr int NJP = NJ / 2;
    __shared__ __align__(16) __half As[GSTAGES][GBM][GBK + 8];
    __shared__ __align__(16) __half Bs[GSTAGES][GBK][BN + 8];

    int tid = threadIdx.x;
    int lane = tid & 31, wid = tid >> 5;
    int wm = wid & 3, wn = wid >> 2;
    int rowBase = blockIdx.y * GBM;
    int colBase = blockIdx.x * BN;

    float acc[2][NJ][4];
    #pragma unroll
    for (int i = 0; i < 2; i++)
        #pragma unroll
        for (int j = 0; j < NJ; j++)
            #pragma unroll
            for (int q = 0; q < 4; q++) acc[i][j][q] = 0.f;

    auto load_stage = [&](int s, int k0) {
        {
            int r = tid >> 1;
            int c8 = (tid & 1) << 3;
            int row = rowBase + r;
            if (row > M - 1) row = M - 1;
            cp_async16(smem_u32(&As[s][r][c8]), A + (size_t)row * K + k0 + c8);
        }
        #pragma unroll
        for (int q = tid; q < 2 * BN; q += 256) {
            int r = q / (BN / 8);
            int c8 = (q % (BN / 8)) << 3;
            cp_async16(smem_u32(&Bs[s][r][c8]), B + (size_t)(k0 + r) * N + colBase + c8);
        }
        cp_commit();
    };

    int T = K / GBK;
    load_stage(0, 0);
    load_stage(1, GBK);
    load_stage(2, 2 * GBK);

    for (int t = 0; t < T; t++) {
        cp_wait<GSTAGES - 2>();
        __syncthreads();
        int pf = t + GSTAGES - 1;
        if (pf < T) load_stage(pf % GSTAGES, pf * GBK);
        int cur = t % GSTAGES;

        uint32_t a[2][4];
        #pragma unroll
        for (int mi = 0; mi < 2; mi++) {
            int r = wm * 32 + mi * 16 + (lane & 15);
            int c = (lane >> 4) << 3;
            ldsm_x4(a[mi], smem_u32(&As[cur][r][c]));
        }
        uint32_t b[NJ][2];
        #pragma unroll
        for (int p = 0; p < NJP; p++) {
            int r = (lane & 7) + (lane & 8);
            int c = wn * WN + p * 16 + ((lane >> 4) << 3);
            uint32_t tt[4];
            ldsm_x4_trans(tt, smem_u32(&Bs[cur][r][c]));
            b[2 * p][0] = tt[0]; b[2 * p][1] = tt[1];
            b[2 * p + 1][0] = tt[2]; b[2 * p + 1][1] = tt[3];
        }
        #pragma unroll
        for (int mi = 0; mi < 2; mi++)
            #pragma unroll
            for (int nj = 0; nj < NJ; nj++)
                mma16816h(acc[mi][nj], a[mi], b[nj]);
    }

    // epilogue
    int g = lane >> 2, tig = lane & 3;
    #pragma unroll
    for (int mi = 0; mi < 2; mi++) {
        int row0 = rowBase + wm * 32 + mi * 16 + g;
        int row1 = row0 + 8;
        #pragma unroll
        for (int nj = 0; nj < NJ; nj++) {
            int col = colBase + wn * WN + nj * 8 + 2 * tig;
            float bv0 = bias[col], bv1 = bias[col + 1];
            float v0 = acc[mi][nj][0] + bv0;
            float v1 = acc[mi][nj][1] + bv1;
            float v2 = acc[mi][nj][2] + bv0;
            float v3 = acc[mi][nj][3] + bv1;
            if (RELU) {
                v0 = fmaxf(v0, 0.f); v1 = fmaxf(v1, 0.f);
                v2 = fmaxf(v2, 0.f); v3 = fmaxf(v3, 0.f);
            }
            if (OUT16) {
                if (row0 < M) *(__half2*)&C16[(size_t)row0 * N + col] = __floats2half2_rn(v0, v1);
                if (row1 < M) *(__half2*)&C16[(size_t)row1 * N + col] = __floats2half2_rn(v2, v3);
            } else {
                if (row0 < M) {
                    Cf[(size_t)row0 * N + col]     = v0;
                    Cf[(size_t)row0 * N + col + 1] = v1;
                }
                if (row1 < M) {
                    Cf[(size_t)row1 * N + col]     = v2;
                    Cf[(size_t)row1 * N + col + 1] = v3;
                }
            }
        }
    }
}

// ------- propagation hop (fp16 storage): half-warp/node, uint2 (4 halves) -
__global__ void prop_kernel(const __half* __restrict__ fin, __half* __restrict__ fout) {
    int node = (blockIdx.x * blockDim.x + threadIdx.x) >> 4;
    if (node >= N_NODES) return;
    int lane = threadIdx.x & 15;
    int beg = g_row_ptr[node], end = g_row_ptr[node + 1];
    float ax = 0.f, ay = 0.f, az = 0.f, aw = 0.f;
    int p = beg;
    for (; p + 2 <= end; p += 2) {
        int s0 = g_csr_src[p];
        int s1 = g_csr_src[p + 1];
        float ns0 = g_nsrc[s0];
        float ns1 = g_nsrc[s1];
        uint2 u0 = ((const uint2*)(fin + (size_t)s0 * OUT_DIM))[lane];
        uint2 u1 = ((const uint2*)(fin + (size_t)s1 * OUT_DIM))[lane];
        float2 f00 = __half22float2(*(__half2*)&u0.x);
        float2 f01 = __half22float2(*(__half2*)&u0.y);
        float2 f10 = __half22float2(*(__half2*)&u1.x);
        float2 f11 = __half22float2(*(__half2*)&u1.y);
        ax += f00.x * ns0 + f10.x * ns1;
        ay += f00.y * ns0 + f10.y * ns1;
        az += f01.x * ns0 + f11.x * ns1;
        aw += f01.y * ns0 + f11.y * ns1;
    }
    if (p < end) {
        int s = g_csr_src[p];
        float ns = g_nsrc[s];
        uint2 u = ((const uint2*)(fin + (size_t)s * OUT_DIM))[lane];
        float2 f0 = __half22float2(*(__half2*)&u.x);
        float2 f1 = __half22float2(*(__half2*)&u.y);
        ax += f0.x * ns; ay += f0.y * ns; az += f1.x * ns; aw += f1.y * ns;
    }
    float nd = (1.f - ALPHA) * g_ndst[node];
    uint2 uz = ((const uint2*)(g_x016 + (size_t)node * OUT_DIM))[lane];
    float2 z0 = __half22float2(*(__half2*)&uz.x);
    float2 z1 = __half22float2(*(__half2*)&uz.y);
    __half2 o0 = __floats2half2_rn(ax * nd + ALPHA * z0.x, ay * nd + ALPHA * z0.y);
    __half2 o1 = __floats2half2_rn(az * nd + ALPHA * z1.x, aw * nd + ALPHA * z1.y);
    uint2 uo;
    uo.x = *(uint32_t*)&o0;
    uo.y = *(uint32_t*)&o1;
    ((uint2*)(fout + (size_t)node * OUT_DIM))[lane] = uo;
}

// ---------------- attention score dots: warp per node (fp16 feat) --------
__global__ void dots_kernel(const __half* __restrict__ feat,
                            const float* __restrict__ wsrc,
                            const float* __restrict__ wdst) {
    int node = (blockIdx.x * blockDim.x + threadIdx.x) >> 5;
    if (node >= N_NODES) return;
    int lane = threadIdx.x & 31;
    float2 f = __half22float2(((const __half2*)(feat + (size_t)node * OUT_DIM))[lane]);
    float2 a = ((const float2*)wsrc)[lane];
    float2 b = ((const float2*)wdst)[lane];
    float s = f.x * a.x + f.y * a.y;
    float d = f.x * b.x + f.y * b.y;
    #pragma unroll
    for (int off = 16; off; off >>= 1) {
        s += __shfl_xor_sync(0xffffffffu, s, off);
        d += __shfl_xor_sync(0xffffffffu, d, off);
    }
    if (lane == 0) {
        g_es[node] = s;
        g_ed[node] = d;
    }
}

// ---------------- attention softmax over in-edges: warp per node ----------
__global__ void attn_kernel(float* __restrict__ attn_out) {
    int node = (blockIdx.x * blockDim.x + threadIdx.x) >> 5;
    if (node >= N_NODES) return;
    int lane = threadIdx.x & 31;
    int beg = g_row_ptr[node], end = g_row_ptr[node + 1];
    int deg = end - beg;
    if (deg == 0) return;
    float edv = g_ed[node];

    if (deg <= 32) {
        int p = beg + lane;
        bool act = p < end;
        float e = act ? tanhf(g_es[g_csr_src[p]] + edv) : -INFINITY;
        float m = e;
        #pragma unroll
        for (int off = 16; off; off >>= 1) m = fmaxf(m, __shfl_xor_sync(0xffffffffu, m, off));
        float ex = act ? expf(e - m) : 0.f;
        float s = ex;
        #pragma unroll
        for (int off = 16; off; off >>= 1) s += __shfl_xor_sync(0xffffffffu, s, off);
        if (act) attn_out[g_csr_eid[p]] = ex / s;
        return;
    }

    float m = -INFINITY;
    for (int p = beg + lane; p < end; p += 32) {
        float e = tanhf(g_es[g_csr_src[p]] + edv);
        g_etmp[p] = e;
        m = fmaxf(m, e);
    }
    #pragma unroll
    for (int off = 16; off; off >>= 1) m = fmaxf(m, __shfl_xor_sync(0xffffffffu, m, off));
    float s = 0.f;
    for (int p = beg + lane; p < end; p += 32) {
        float ex = expf(g_etmp[p] - m);
        g_etmp[p] = ex;
        s += ex;
    }
    #pragma unroll
    for (int off = 16; off; off >>= 1) s += __shfl_xor_sync(0xffffffffu, s, off);
    float inv = 1.f / s;
    for (int p = beg + lane; p < end; p += 32) {
        attn_out[g_csr_eid[p]] = g_etmp[p] * inv;
    }
}

// ---------------- log_softmax over 64 features: warp per node (fp16) ------
__global__ void lsm_kernel(const __half* __restrict__ feat, float* __restrict__ out) {
    int node = (blockIdx.x * blockDim.x + threadIdx.x) >> 5;
    if (node >= N_NODES) return;
    int lane = threadIdx.x & 31;
    float2 f = __half22float2(((const __half2*)(feat + (size_t)node * OUT_DIM))[lane]);
    float m = fmaxf(f.x, f.y);
    #pragma unroll
    for (int off = 16; off; off >>= 1) m = fmaxf(m, __shfl_xor_sync(0xffffffffu, m, off));
    float s = expf(f.x - m) + expf(f.y - m);
    #pragma unroll
    for (int off = 16; off; off >>= 1) s += __shfl_xor_sync(0xffffffffu, s, off);
    float lse = m + logf(s);
    float2 o;
    o.x = f.x - lse;
    o.y = f.y - lse;
    ((float2*)(out + (size_t)node * OUT_DIM))[lane] = o;
}

// ---------------- launch ----------------
extern "C" void kernel_launch(void* const* d_in, const int* in_sizes, int n_in,
                              void* d_out, int out_size) {
    const float* h   = (const float*)d_in[0];
    const int*   src = (const int*)d_in[1];
    const int*   dst = (const int*)d_in[2];
    const float* W1  = (const float*)d_in[3];
    const float* b1  = (const float*)d_in[4];
    const float* W2  = (const float*)d_in[5];
    const float* b2  = (const float*)d_in[6];
    const float* wsr = (const float*)d_in[7];
    const float* wds = (const float*)d_in[8];
    float* out = (float*)d_out;

    __half *p_h16, *p_w1, *p_w2, *p_hid16, *p_x016, *p_fA16, *p_fB16;
    cudaGetSymbolAddress((void**)&p_h16, g_h16);
    cudaGetSymbolAddress((void**)&p_w1, g_w1);
    cudaGetSymbolAddress((void**)&p_w2, g_w2);
    cudaGetSymbolAddress((void**)&p_hid16, g_hid16);
    cudaGetSymbolAddress((void**)&p_x016, g_x016);
    cudaGetSymbolAddress((void**)&p_fA16, g_fA16);
    cudaGetSymbolAddress((void**)&p_fB16, g_fB16);

    const int TPB = 256;
    int nodeBlocks = (N_NODES + TPB - 1) / TPB;
    int edgeBlocks = (N_EDGES + TPB - 1) / TPB;
    int warpNodeBlocks = (N_NODES * 32 + TPB - 1) / TPB;
    int hwNodeBlocks = (N_NODES * 16 + TPB - 1) / TPB;

    // 1-3: zero + conversions (gemm1 kept in ncu capture slot 4)
    zero3_kernel<<<nodeBlocks, TPB>>>();
    {
        int n4 = N_NODES * IN_DIM / 4;
        f32_to_f16_kernel<<<(n4 + TPB - 1) / TPB, TPB>>>(h, p_h16, n4);
        int w4 = IN_DIM * HID_DIM / 4;
        f32_to_f16_kernel<<<(w4 + TPB - 1) / TPB, TPB>>>(W1, p_w1, w4);
    }

    // 4: GEMM1  hidden16 = fp16(relu(h @ W1 + b1))
    {
        dim3 grid1(HID_DIM / 128, (N_NODES + GBM - 1) / GBM);
        gemm_f16_kernel<128, true, true><<<grid1, 256>>>(
            p_h16, p_w1, b1, nullptr, p_hid16, N_NODES, HID_DIM, IN_DIM);
    }

    {
        int w4 = HID_DIM * OUT_DIM / 4;
        f32_to_f16_kernel<<<(w4 + TPB - 1) / TPB, TPB>>>(W2, p_w2, w4);
    }
    count_deg_kernel<<<edgeBlocks, TPB>>>(src, dst);
    norm_kernel<<<nodeBlocks, TPB>>>();
    scan1_kernel<<<SCAN_NBLK, SCAN_BLK>>>();
    scan2_kernel<<<1, 1>>>();
    scan3_kernel<<<SCAN_NBLK, SCAN_BLK>>>();
    build_csr_kernel<<<edgeBlocks, TPB>>>(src, dst);

    // GEMM2  x0(fp16) = hidden @ W2 + b2
    {
        dim3 grid2(OUT_DIM / 64, (N_NODES + GBM - 1) / GBM);
        gemm_f16_kernel<64, false, true><<<grid2, 256>>>(
            p_hid16, p_w2, b2, nullptr, p_x016, N_NODES, OUT_DIM, HID_DIM);
    }

    // K_HOPS=4 propagation (fp16 storage), ping-pong; final result in g_fB16
    prop_kernel<<<hwNodeBlocks, TPB>>>(p_x016, p_fA16);
    prop_kernel<<<hwNodeBlocks, TPB>>>(p_fA16, p_fB16);
    prop_kernel<<<hwNodeBlocks, TPB>>>(p_fB16, p_fA16);
    prop_kernel<<<hwNodeBlocks, TPB>>>(p_fA16, p_fB16);

    // attention
    dots_kernel<<<warpNodeBlocks, TPB>>>(p_fB16, wsr, wds);
    attn_kernel<<<warpNodeBlocks, TPB>>>(out + (size_t)N_NODES * OUT_DIM);

    // log_softmax output
    lsm_kernel<<<warpNodeBlocks, TPB>>>(p_fB16, out);
}

// round 9
// speedup vs baseline: 2.3818x; 1.1127x over previous
#include <cuda_runtime.h>
#include <cuda_bf16.h>
#include <cuda_fp16.h>
#include <math.h>
#include <stdint.h>

#define N_NODES 50000
#define N_EDGES 1600000
#define IN_DIM 512
#define HID_DIM 256
#define OUT_DIM 64
#define K_HOPS 4
#define ALPHA 0.1f

#define SCAN_BLK 1024
#define SCAN_NBLK ((N_NODES + SCAN_BLK - 1) / SCAN_BLK)   // 49

// ---------------- device scratch (no allocs allowed) ----------------
__device__ __half  g_h16[(size_t)N_NODES * IN_DIM];
__device__ __half  g_w1[IN_DIM * HID_DIM];
__device__ __half  g_w2[HID_DIM * OUT_DIM];
__device__ __half  g_hid16[(size_t)N_NODES * HID_DIM];
__device__ __half  g_x016[(size_t)N_NODES * OUT_DIM];   // feat0 fp16 (unscaled)
__device__ __half  g_x0s[(size_t)N_NODES * OUT_DIM];    // feat0 * nsrc
__device__ __half  g_fA16[(size_t)N_NODES * OUT_DIM];
__device__ __half  g_fAs[(size_t)N_NODES * OUT_DIM];
__device__ __half  g_fB16[(size_t)N_NODES * OUT_DIM];
__device__ __half  g_fBs[(size_t)N_NODES * OUT_DIM];
__device__ int   g_deg_out[N_NODES];
__device__ int   g_deg_in[N_NODES];
__device__ int   g_fill[N_NODES];
__device__ int   g_row_ptr[N_NODES + 1];
__device__ float g_nsrc[N_NODES];
__device__ float g_ndst[N_NODES];
__device__ int   g_csr_src[N_EDGES];
__device__ int   g_csr_eid[N_EDGES];
__device__ float g_es[N_NODES];
__device__ float g_ed[N_NODES];
__device__ float g_etmp[N_EDGES];
__device__ int   g_bsum[SCAN_NBLK];
__device__ int   g_boff[SCAN_NBLK];

// ---------------- conversion kernel ----------------
__global__ void f32_to_f16_kernel(const float* __restrict__ in,
                                  __half* __restrict__ out, int n4) {
    int i = blockIdx.x * blockDim.x + threadIdx.x;
    if (i < n4) {
        float4 v = ((const float4*)in)[i];
        __half2 a = __floats2half2_rn(v.x, v.y);
        __half2 b = __floats2half2_rn(v.z, v.w);
        uint2 u;
        u.x = *(uint32_t*)&a;
        u.y = *(uint32_t*)&b;
        ((uint2*)out)[i] = u;
    }
}

// ---------------- small kernels ----------------
__global__ void zero3_kernel() {
    int i = blockIdx.x * blockDim.x + threadIdx.x;
    if (i < N_NODES) {
        g_deg_out[i] = 0;
        g_deg_in[i]  = 0;
        g_fill[i]    = 0;
    }
}

__global__ void count_deg_kernel(const int* __restrict__ src, const int* __restrict__ dst) {
    int e = blockIdx.x * blockDim.x + threadIdx.x;
    if (e < N_EDGES) {
        atomicAdd(&g_deg_out[src[e]], 1);
        atomicAdd(&g_deg_in[dst[e]], 1);
    }
}

__global__ void norm_kernel() {
    int i = blockIdx.x * blockDim.x + threadIdx.x;
    if (i < N_NODES) {
        int doo = g_deg_out[i]; if (doo < 1) doo = 1;
        int din = g_deg_in[i];  if (din < 1) din = 1;
        g_nsrc[i] = rsqrtf((float)doo);
        g_ndst[i] = rsqrtf((float)din);
    }
}

// ---- 3-phase grid-wide exclusive scan of g_deg_in -> g_row_ptr ----
__global__ void scan1_kernel() {
    __shared__ int warpsum[32];
    int tid = threadIdx.x, lane = tid & 31, wid = tid >> 5;
    int i = blockIdx.x * SCAN_BLK + tid;
    int v = (i < N_NODES) ? g_deg_in[i] : 0;
    int x = v;
    #pragma unroll
    for (int off = 1; off < 32; off <<= 1) {
        int t = __shfl_up_sync(0xffffffffu, x, off);
        if (lane >= off) x += t;
    }
    if (lane == 31) warpsum[wid] = x;
    __syncthreads();
    if (wid == 0) {
        int w = warpsum[lane];
        #pragma unroll
        for (int off = 1; off < 32; off <<= 1) {
            int t = __shfl_up_sync(0xffffffffu, w, off);
            if (lane >= off) w += t;
        }
        warpsum[lane] = w;
    }
    __syncthreads();
    int offset = (wid > 0) ? warpsum[wid - 1] : 0;
    if (i < N_NODES) g_row_ptr[i] = x + offset - v;
    if (tid == SCAN_BLK - 1) g_bsum[blockIdx.x] = x + offset;
}

// warp-parallel scan of the 49 block sums
__global__ void scan2_kernel() {
    int lane = threadIdx.x;
    int carry = 0;
    for (int base = 0; base < SCAN_NBLK; base += 32) {
        int i = base + lane;
        int v = (i < SCAN_NBLK) ? g_bsum[i] : 0;
        int x = v;
        #pragma unroll
        for (int off = 1; off < 32; off <<= 1) {
            int t = __shfl_up_sync(0xffffffffu, x, off);
            if (lane >= off) x += t;
        }
        if (i < SCAN_NBLK) g_boff[i] = carry + x - v;
        carry += __shfl_sync(0xffffffffu, x, 31);
    }
    if (lane == 0) g_row_ptr[N_NODES] = carry;
}

__global__ void scan3_kernel() {
    int i = blockIdx.x * SCAN_BLK + threadIdx.x;
    if (i < N_NODES && blockIdx.x > 0) g_row_ptr[i] += g_boff[blockIdx.x];
}

__global__ void build_csr_kernel(const int* __restrict__ src, const int* __restrict__ dst) {
    int e = blockIdx.x * blockDim.x + threadIdx.x;
    if (e < N_EDGES) {
        int d = dst[e];
        int pos = g_row_ptr[d] + atomicAdd(&g_fill[d], 1);
        g_csr_src[pos] = src[e];
        g_csr_eid[pos] = e;
    }
}

// ---------------- fp16 tensor-core GEMM, 4-stage cp.async, static smem ---
__device__ __forceinline__ uint32_t smem_u32(const void* p) {
    return (uint32_t)__cvta_generic_to_shared(p);
}
__device__ __forceinline__ void cp_async16(uint32_t s, const void* g) {
    asm volatile("cp.async.cg.shared.global [%0], [%1], 16;\n"
        :: "r"(s), "l"(__cvta_generic_to_global(g)));
}
__device__ __forceinline__ void cp_commit() {
    asm volatile("cp.async.commit_group;\n");
}
template <int NW>
__device__ __forceinline__ void cp_wait() {
    asm volatile("cp.async.wait_group %0;\n" :: "n"(NW));
}
__device__ __forceinline__ void ldsm_x4(uint32_t* r, uint32_t addr) {
    asm volatile("ldmatrix.sync.aligned.m8n8.x4.shared.b16 {%0,%1,%2,%3}, [%4];\n"
        : "=r"(r[0]), "=r"(r[1]), "=r"(r[2]), "=r"(r[3]) : "r"(addr));
}
__device__ __forceinline__ void ldsm_x4_trans(uint32_t* r, uint32_t addr) {
    asm volatile("ldmatrix.sync.aligned.m8n8.x4.trans.shared.b16 {%0,%1,%2,%3}, [%4];\n"
        : "=r"(r[0]), "=r"(r[1]), "=r"(r[2]), "=r"(r[3]) : "r"(addr));
}
__device__ __forceinline__ void mma16816h(float* c, const uint32_t* a, const uint32_t* b) {
    asm volatile(
        "mma.sync.aligned.m16n8k16.row.col.f32.f16.f16.f32 "
        "{%0,%1,%2,%3}, {%4,%5,%6,%7}, {%8,%9}, {%0,%1,%2,%3};\n"
        : "+f"(c[0]), "+f"(c[1]), "+f"(c[2]), "+f"(c[3])
        : "r"(a[0]), "r"(a[1]), "r"(a[2]), "r"(a[3]), "r"(b[0]), "r"(b[1]));
}

#define GBM 128
#define GBK 16
#define GSTAGES 4

template <int BN, bool RELU, bool OUT16>
__global__ __launch_bounds__(256)
void gemm_f16_kernel(const __half* __restrict__ A,
                     const __half* __restrict__ B,
                     const float* __restrict__ bias,
                     float* __restrict__ Cf,
                     __half* __restrict__ C16,
                     int M, int N, int K) {
    constexpr int WN  = BN / 2;
    constexpr int NJ  = WN / 8;
    constexpr int NJP = NJ / 2;
    __shared__ __align__(16) __half As[GSTAGES][GBM][GBK + 8];
    __shared__ __align__(16) __half Bs[GSTAGES][GBK][BN + 8];

    int tid = threadIdx.x;
    int lane = tid & 31, wid = tid >> 5;
    int wm = wid & 3, wn = wid >> 2;
    int rowBase = blockIdx.y * GBM;
    int colBase = blockIdx.x * BN;

    float acc[2][NJ][4];
    #pragma unroll
    for (int i = 0; i < 2; i++)
        #pragma unroll
        for (int j = 0; j < NJ; j++)
            #pragma unroll
            for (int q = 0; q < 4; q++) acc[i][j][q] = 0.f;

    auto load_stage = [&](int s, int k0) {
        {
            int r = tid >> 1;
            int c8 = (tid & 1) << 3;
            int row = rowBase + r;
            if (row > M - 1) row = M - 1;
            cp_async16(smem_u32(&As[s][r][c8]), A + (size_t)row * K + k0 + c8);
        }
        #pragma unroll
        for (int q = tid; q < 2 * BN; q += 256) {
            int r = q / (BN / 8);
            int c8 = (q % (BN / 8)) << 3;
            cp_async16(smem_u32(&Bs[s][r][c8]), B + (size_t)(k0 + r) * N + colBase + c8);
        }
        cp_commit();
    };

    int T = K / GBK;
    load_stage(0, 0);
    load_stage(1, GBK);
    load_stage(2, 2 * GBK);

    for (int t = 0; t < T; t++) {
        cp_wait<GSTAGES - 2>();
        __syncthreads();
        int pf = t + GSTAGES - 1;
        if (pf < T) load_stage(pf % GSTAGES, pf * GBK);
        int cur = t % GSTAGES;

        uint32_t a[2][4];
        #pragma unroll
        for (int mi = 0; mi < 2; mi++) {
            int r = wm * 32 + mi * 16 + (lane & 15);
            int c = (lane >> 4) << 3;
            ldsm_x4(a[mi], smem_u32(&As[cur][r][c]));
        }
        uint32_t b[NJ][2];
        #pragma unroll
        for (int p = 0; p < NJP; p++) {
            int r = (lane & 7) + (lane & 8);
            int c = wn * WN + p * 16 + ((lane >> 4) << 3);
            uint32_t tt[4];
            ldsm_x4_trans(tt, smem_u32(&Bs[cur][r][c]));
            b[2 * p][0] = tt[0]; b[2 * p][1] = tt[1];
            b[2 * p + 1][0] = tt[2]; b[2 * p + 1][1] = tt[3];
        }
        #pragma unroll
        for (int mi = 0; mi < 2; mi++)
            #pragma unroll
            for (int nj = 0; nj < NJ; nj++)
                mma16816h(acc[mi][nj], a[mi], b[nj]);
    }

    int g = lane >> 2, tig = lane & 3;
    #pragma unroll
    for (int mi = 0; mi < 2; mi++) {
        int row0 = rowBase + wm * 32 + mi * 16 + g;
        int row1 = row0 + 8;
        #pragma unroll
        for (int nj = 0; nj < NJ; nj++) {
            int col = colBase + wn * WN + nj * 8 + 2 * tig;
            float bv0 = bias[col], bv1 = bias[col + 1];
            float v0 = acc[mi][nj][0] + bv0;
            float v1 = acc[mi][nj][1] + bv1;
            float v2 = acc[mi][nj][2] + bv0;
            float v3 = acc[mi][nj][3] + bv1;
            if (RELU) {
                v0 = fmaxf(v0, 0.f); v1 = fmaxf(v1, 0.f);
                v2 = fmaxf(v2, 0.f); v3 = fmaxf(v3, 0.f);
            }
            if (OUT16) {
                if (row0 < M) *(__half2*)&C16[(size_t)row0 * N + col] = __floats2half2_rn(v0, v1);
                if (row1 < M) *(__half2*)&C16[(size_t)row1 * N + col] = __floats2half2_rn(v2, v3);
            } else {
                if (row0 < M) {
                    Cf[(size_t)row0 * N + col]     = v0;
                    Cf[(size_t)row0 * N + col + 1] = v1;
                }
                if (row1 < M) {
                    Cf[(size_t)row1 * N + col]     = v2;
                    Cf[(size_t)row1 * N + col + 1] = v3;
                }
            }
        }
    }
}

// ------- pre-scale x0: x0s = x016 * nsrc (8 lanes/node, uint4) ------------
__global__ void scale_x0_kernel() {
    int i = blockIdx.x * blockDim.x + threadIdx.x;
    if (i >= N_NODES * 8) return;
    int node = i >> 3;
    float ns = g_nsrc[node];
    uint4 u = ((const uint4*)g_x016)[i];
    __half2* h = (__half2*)&u;
    uint4 o;
    __half2* ho = (__half2*)&o;
    #pragma unroll
    for (int q = 0; q < 4; q++) {
        float2 f = __half22float2(h[q]);
        ho[q] = __floats2half2_rn(f.x * ns, f.y * ns);
    }
    ((uint4*)g_x0s)[i] = o;
}

// ------- propagation hop: 8 lanes/node, pre-scaled input, pure gather-add -
__device__ __forceinline__ void acc8(float* a, uint4 u) {
    __half2* h = (__half2*)&u;
    #pragma unroll
    for (int q = 0; q < 4; q++) {
        float2 f = __half22float2(h[q]);
        a[2 * q]     += f.x;
        a[2 * q + 1] += f.y;
    }
}

template <bool WRITE_SCALED>
__global__ void prop_kernel(const __half* __restrict__ fin_s,
                            __half* __restrict__ fout,
                            __half* __restrict__ fout_s) {
    int t = blockIdx.x * blockDim.x + threadIdx.x;
    int node = t >> 3;
    if (node >= N_NODES) return;
    int lane = t & 7;
    int beg = g_row_ptr[node], end = g_row_ptr[node + 1];
    float a[8] = {0.f, 0.f, 0.f, 0.f, 0.f, 0.f, 0.f, 0.f};
    int p = beg;
    for (; p + 4 <= end; p += 4) {
        int s0 = g_csr_src[p];
        int s1 = g_csr_src[p + 1];
        int s2 = g_csr_src[p + 2];
        int s3 = g_csr_src[p + 3];
        uint4 u0 = ((const uint4*)(fin_s + (size_t)s0 * OUT_DIM))[lane];
        uint4 u1 = ((const uint4*)(fin_s + (size_t)s1 * OUT_DIM))[lane];
        uint4 u2 = ((const uint4*)(fin_s + (size_t)s2 * OUT_DIM))[lane];
        uint4 u3 = ((const uint4*)(fin_s + (size_t)s3 * OUT_DIM))[lane];
        acc8(a, u0); acc8(a, u1); acc8(a, u2); acc8(a, u3);
    }
    for (; p < end; p++) {
        int s = g_csr_src[p];
        acc8(a, ((const uint4*)(fin_s + (size_t)s * OUT_DIM))[lane]);
    }
    float nd = (1.f - ALPHA) * g_ndst[node];
    uint4 uz = ((const uint4*)(g_x016 + (size_t)node * OUT_DIM))[lane];
    __half2* hz = (__half2*)&uz;
    float o[8];
    #pragma unroll
    for (int q = 0; q < 4; q++) {
        float2 z = __half22float2(hz[q]);
        o[2 * q]     = a[2 * q] * nd + ALPHA * z.x;
        o[2 * q + 1] = a[2 * q + 1] * nd + ALPHA * z.y;
    }
    uint4 uo;
    __half2* ho = (__half2*)&uo;
    #pragma unroll
    for (int q = 0; q < 4; q++)
        ho[q] = __floats2half2_rn(o[2 * q], o[2 * q + 1]);
    ((uint4*)(fout + (size_t)node * OUT_DIM))[lane] = uo;
    if (WRITE_SCALED) {
        float ns = g_nsrc[node];
        uint4 us;
        __half2* hs = (__half2*)&us;
        #pragma unroll
        for (int q = 0; q < 4; q++)
            hs[q] = __floats2half2_rn(o[2 * q] * ns, o[2 * q + 1] * ns);
        ((uint4*)(fout_s + (size_t)node * OUT_DIM))[lane] = us;
    }
}

// ---------------- attention score dots: warp per node (fp16 feat) --------
__global__ void dots_kernel(const __half* __restrict__ feat,
                            const float* __restrict__ wsrc,
                            const float* __restrict__ wdst) {
    int node = (blockIdx.x * blockDim.x + threadIdx.x) >> 5;
    if (node >= N_NODES) return;
    int lane = threadIdx.x & 31;
    float2 f = __half22float2(((const __half2*)(feat + (size_t)node * OUT_DIM))[lane]);
    float2 a = ((const float2*)wsrc)[lane];
    float2 b = ((const float2*)wdst)[lane];
    float s = f.x * a.x + f.y * a.y;
    float d = f.x * b.x + f.y * b.y;
    #pragma unroll
    for (int off = 16; off; off >>= 1) {
        s += __shfl_xor_sync(0xffffffffu, s, off);
        d += __shfl_xor_sync(0xffffffffu, d, off);
    }
    if (lane == 0) {
        g_es[node] = s;
        g_ed[node] = d;
    }
}

// ---------------- attention softmax over in-edges: warp per node ----------
__global__ void attn_kernel(float* __restrict__ attn_out) {
    int node = (blockIdx.x * blockDim.x + threadIdx.x) >> 5;
    if (node >= N_NODES) return;
    int lane = threadIdx.x & 31;
    int beg = g_row_ptr[node], end = g_row_ptr[node + 1];
    int deg = end - beg;
    if (deg == 0) return;
    float edv = g_ed[node];

    if (deg <= 64) {
        // register path: up to 2 edges per lane, fully in-register
        int p0 = beg + lane, p1 = beg + 32 + lane;
        bool a0 = p0 < end, a1 = p1 < end;
        float e0 = a0 ? tanhf(g_es[g_csr_src[p0]] + edv) : -INFINITY;
        float e1 = a1 ? tanhf(g_es[g_csr_src[p1]] + edv) : -INFINITY;
        float m = fmaxf(e0, e1);
        #pragma unroll
        for (int off = 16; off; off >>= 1) m = fmaxf(m, __shfl_xor_sync(0xffffffffu, m, off));
        float x0 = a0 ? expf(e0 - m) : 0.f;
        float x1 = a1 ? expf(e1 - m) : 0.f;
        float s = x0 + x1;
        #pragma unroll
        for (int off = 16; off; off >>= 1) s += __shfl_xor_sync(0xffffffffu, s, off);
        float inv = 1.f / s;
        if (a0) attn_out[g_csr_eid[p0]] = x0 * inv;
        if (a1) attn_out[g_csr_eid[p1]] = x1 * inv;
        return;
    }

    float m = -INFINITY;
    for (int p = beg + lane; p < end; p += 32) {
        float e = tanhf(g_es[g_csr_src[p]] + edv);
        g_etmp[p] = e;
        m = fmaxf(m, e);
    }
    #pragma unroll
    for (int off = 16; off; off >>= 1) m = fmaxf(m, __shfl_xor_sync(0xffffffffu, m, off));
    float s = 0.f;
    for (int p = beg + lane; p < end; p += 32) {
        float ex = expf(g_etmp[p] - m);
        g_etmp[p] = ex;
        s += ex;
    }
    #pragma unroll
    for (int off = 16; off; off >>= 1) s += __shfl_xor_sync(0xffffffffu, s, off);
    float inv = 1.f / s;
    for (int p = beg + lane; p < end; p += 32) {
        attn_out[g_csr_eid[p]] = g_etmp[p] * inv;
    }
}

// ---------------- log_softmax over 64 features: warp per node (fp16) ------
__global__ void lsm_kernel(const __half* __restrict__ feat, float* __restrict__ out) {
    int node = (blockIdx.x * blockDim.x + threadIdx.x) >> 5;
    if (node >= N_NODES) return;
    int lane = threadIdx.x & 31;
    float2 f = __half22float2(((const __half2*)(feat + (size_t)node * OUT_DIM))[lane]);
    float m = fmaxf(f.x, f.y);
    #pragma unroll
    for (int off = 16; off; off >>= 1) m = fmaxf(m, __shfl_xor_sync(0xffffffffu, m, off));
    float s = expf(f.x - m) + expf(f.y - m);
    #pragma unroll
    for (int off = 16; off; off >>= 1) s += __shfl_xor_sync(0xffffffffu, s, off);
    float lse = m + logf(s);
    float2 o;
    o.x = f.x - lse;
    o.y = f.y - lse;
    ((float2*)(out + (size_t)node * OUT_DIM))[lane] = o;
}

// ---------------- launch ----------------
extern "C" void kernel_launch(void* const* d_in, const int* in_sizes, int n_in,
                              void* d_out, int out_size) {
    const float* h   = (const float*)d_in[0];
    const int*   src = (const int*)d_in[1];
    const int*   dst = (const int*)d_in[2];
    const float* W1  = (const float*)d_in[3];
    const float* b1  = (const float*)d_in[4];
    const float* W2  = (const float*)d_in[5];
    const float* b2  = (const float*)d_in[6];
    const float* wsr = (const float*)d_in[7];
    const float* wds = (const float*)d_in[8];
    float* out = (float*)d_out;

    __half *p_h16, *p_w1, *p_w2, *p_hid16, *p_x016, *p_x0s, *p_fA, *p_fAs, *p_fB, *p_fBs;
    cudaGetSymbolAddress((void**)&p_h16, g_h16);
    cudaGetSymbolAddress((void**)&p_w1, g_w1);
    cudaGetSymbolAddress((void**)&p_w2, g_w2);
    cudaGetSymbolAddress((void**)&p_hid16, g_hid16);
    cudaGetSymbolAddress((void**)&p_x016, g_x016);
    cudaGetSymbolAddress((void**)&p_x0s, g_x0s);
    cudaGetSymbolAddress((void**)&p_fA, g_fA16);
    cudaGetSymbolAddress((void**)&p_fAs, g_fAs);
    cudaGetSymbolAddress((void**)&p_fB, g_fB16);
    cudaGetSymbolAddress((void**)&p_fBs, g_fBs);

    const int TPB = 256;
    int nodeBlocks = (N_NODES + TPB - 1) / TPB;
    int edgeBlocks = (N_EDGES + TPB - 1) / TPB;
    int warpNodeBlocks = (N_NODES * 32 + TPB - 1) / TPB;
    int octNodeBlocks = (N_NODES * 8 + TPB - 1) / TPB;

    // 1-3: zero + conversions (gemm1 kept in ncu capture slot 4)
    zero3_kernel<<<nodeBlocks, TPB>>>();
    {
        int n4 = N_NODES * IN_DIM / 4;
        f32_to_f16_kernel<<<(n4 + TPB - 1) / TPB, TPB>>>(h, p_h16, n4);
        int w4 = IN_DIM * HID_DIM / 4;
        f32_to_f16_kernel<<<(w4 + TPB - 1) / TPB, TPB>>>(W1, p_w1, w4);
    }

    // 4: GEMM1  hidden16 = fp16(relu(h @ W1 + b1))
    {
        dim3 grid1(HID_DIM / 128, (N_NODES + GBM - 1) / GBM);
        gemm_f16_kernel<128, true, true><<<grid1, 256>>>(
            p_h16, p_w1, b1, nullptr, p_hid16, N_NODES, HID_DIM, IN_DIM);
    }

    {
        int w4 = HID_DIM * OUT_DIM / 4;
        f32_to_f16_kernel<<<(w4 + TPB - 1) / TPB, TPB>>>(W2, p_w2, w4);
    }
    count_deg_kernel<<<edgeBlocks, TPB>>>(src, dst);
    norm_kernel<<<nodeBlocks, TPB>>>();
    scan1_kernel<<<SCAN_NBLK, SCAN_BLK>>>();
    scan2_kernel<<<1, 32>>>();
    scan3_kernel<<<SCAN_NBLK, SCAN_BLK>>>();
    build_csr_kernel<<<edgeBlocks, TPB>>>(src, dst);

    // GEMM2  x0(fp16) = hidden @ W2 + b2, then pre-scale
    {
        dim3 grid2(OUT_DIM / 64, (N_NODES + GBM - 1) / GBM);
        gemm_f16_kernel<64, false, true><<<grid2, 256>>>(
            p_hid16, p_w2, b2, nullptr, p_x016, N_NODES, OUT_DIM, HID_DIM);
    }
    scale_x0_kernel<<<octNodeBlocks, TPB>>>();

    // K_HOPS=4 propagation over scaled buffers; final unscaled in g_fB16
    prop_kernel<true><<<octNodeBlocks, TPB>>>(p_x0s, p_fA, p_fAs);
    prop_kernel<true><<<octNodeBlocks, TPB>>>(p_fAs, p_fB, p_fBs);
    prop_kernel<true><<<octNodeBlocks, TPB>>>(p_fBs, p_fA, p_fAs);
    prop_kernel<false><<<octNodeBlocks, TPB>>>(p_fAs, p_fB, nullptr);

    // attention
    dots_kernel<<<warpNodeBlocks, TPB>>>(p_fB, wsr, wds);
    attn_kernel<<<warpNodeBlocks, TPB>>>(out + (size_t)N_NODES * OUT_DIM);

    // log_softmax output
    lsm_kernel<<<warpNodeBlocks, TPB>>>(p_fB, out);
}